// round 1
// baseline (speedup 1.0000x reference)
#include <cuda_runtime.h>
#include <cstddef>

#define D_MODEL 1024
#define SEQ     2048
#define BATCH   2
#define NHEAD   16
#define HDIM    64
#define MTOT    (BATCH * SEQ)          // 4096 rows

// ---------------------------------------------------------------------------
// Scratch (no cudaMalloc allowed): Q, K, V, attention-output buffers
// ---------------------------------------------------------------------------
__device__ float g_Q[MTOT * D_MODEL];
__device__ float g_K[MTOT * D_MODEL];
__device__ float g_V[MTOT * D_MODEL];
__device__ float g_O[MTOT * D_MODEL];

// ---------------------------------------------------------------------------
// GEMM: C[M,N] = A[M,K] @ W[N,K]^T + bias[N]   (torch Linear semantics)
// 128x128 tile, BK=16, 256 threads, 8x8 micro-tile per thread.
// ---------------------------------------------------------------------------
#define BM 128
#define BN 128
#define BK 16
#define APAD 132   // BM + 4 pad (keeps float4 alignment: 132*4 % 16 == 0)

__global__ __launch_bounds__(256) void gemm_bias_kernel(
    const float* __restrict__ A, const float* __restrict__ W,
    const float* __restrict__ bias, float* __restrict__ C,
    int M, int N, int K)
{
    __shared__ float As[BK][APAD];
    __shared__ float Ws[BK][APAD];

    const int bn = blockIdx.x * BN;
    const int bm = blockIdx.y * BM;
    const int tid = threadIdx.x;
    const int tm = tid >> 4;     // 0..15
    const int tn = tid & 15;     // 0..15

    float acc[8][8];
#pragma unroll
    for (int i = 0; i < 8; i++)
#pragma unroll
        for (int j = 0; j < 8; j++) acc[i][j] = 0.0f;

    for (int k0 = 0; k0 < K; k0 += BK) {
        // Load A tile (128x16) and W tile (128x16), store transposed (k-major).
#pragma unroll
        for (int it = 0; it < 2; it++) {
            int idx = tid + it * 256;        // 0..511 float4 slots
            int r   = idx >> 2;              // 0..127
            int c4  = idx & 3;               // 0..3
            float4 va = *(const float4*)(A + (size_t)(bm + r) * K + k0 + c4 * 4);
            As[c4 * 4 + 0][r] = va.x;
            As[c4 * 4 + 1][r] = va.y;
            As[c4 * 4 + 2][r] = va.z;
            As[c4 * 4 + 3][r] = va.w;
            float4 vw = *(const float4*)(W + (size_t)(bn + r) * K + k0 + c4 * 4);
            Ws[c4 * 4 + 0][r] = vw.x;
            Ws[c4 * 4 + 1][r] = vw.y;
            Ws[c4 * 4 + 2][r] = vw.z;
            Ws[c4 * 4 + 3][r] = vw.w;
        }
        __syncthreads();

#pragma unroll
        for (int kk = 0; kk < BK; kk++) {
            float a[8], b[8];
            float4 a0 = *(const float4*)&As[kk][tm * 8];
            float4 a1 = *(const float4*)&As[kk][tm * 8 + 4];
            float4 b0 = *(const float4*)&Ws[kk][tn * 8];
            float4 b1 = *(const float4*)&Ws[kk][tn * 8 + 4];
            a[0]=a0.x; a[1]=a0.y; a[2]=a0.z; a[3]=a0.w;
            a[4]=a1.x; a[5]=a1.y; a[6]=a1.z; a[7]=a1.w;
            b[0]=b0.x; b[1]=b0.y; b[2]=b0.z; b[3]=b0.w;
            b[4]=b1.x; b[5]=b1.y; b[6]=b1.z; b[7]=b1.w;
#pragma unroll
            for (int i = 0; i < 8; i++)
#pragma unroll
                for (int j = 0; j < 8; j++)
                    acc[i][j] = fmaf(a[i], b[j], acc[i][j]);
        }
        __syncthreads();
    }

    // Epilogue: add bias, write.
    float bv[8];
#pragma unroll
    for (int j = 0; j < 8; j++) bv[j] = bias[bn + tn * 8 + j];
#pragma unroll
    for (int i = 0; i < 8; i++) {
        float* Crow = C + (size_t)(bm + tm * 8 + i) * N + bn + tn * 8;
        float4 o0 = make_float4(acc[i][0] + bv[0], acc[i][1] + bv[1],
                                acc[i][2] + bv[2], acc[i][3] + bv[3]);
        float4 o1 = make_float4(acc[i][4] + bv[4], acc[i][5] + bv[5],
                                acc[i][6] + bv[6], acc[i][7] + bv[7]);
        *(float4*)(Crow)     = o0;
        *(float4*)(Crow + 4) = o1;
    }
}

// ---------------------------------------------------------------------------
// Flash attention (fp32, causal). 64x64 Q tile per block, 64-key steps.
// 256 threads; thread (tr,tc) owns 4x4 micro-tile: rows tr*4+i, cols tc*4+j.
// Row-group (16 threads sharing rows) is a half-warp -> shfl_xor reductions.
// All smem arrays laid out so every access is a contiguous float4.
// ---------------------------------------------------------------------------
#define ROWW 68     // 64 + 4 pad (68*4 bytes = 272, multiple of 16)

__global__ __launch_bounds__(256) void attn_kernel(
    const float* __restrict__ Q, const float* __restrict__ K,
    const float* __restrict__ V, float* __restrict__ O)
{
    extern __shared__ float sm[];
    float* Qst = sm;                 // [64][ROWW]  d-major:  Qst[d][qi]
    float* Kst = Qst + 64 * ROWW;    // [64][ROWW]  d-major:  Kst[d][kj]
    float* Vs  = Kst + 64 * ROWW;    // [64][ROWW]  row-major: Vs[kj][d]
    float* Pst = Vs  + 64 * ROWW;    // [64][ROWW]  col-major: Pst[kj][qi]

    const int qt = (int)gridDim.x - 1 - (int)blockIdx.x;  // long blocks first
    const int h  = blockIdx.y;
    const int b  = blockIdx.z;
    const int tid = threadIdx.x;
    const int tr = tid >> 4;   // 0..15
    const int tc = tid & 15;   // 0..15
    const int q0 = qt * 64;

    const size_t base = (size_t)b * SEQ * D_MODEL + (size_t)h * HDIM;
    const float* Qb = Q + base;
    const float* Kb = K + base;
    const float* Vb = V + base;

    // Load Q tile (transposed, pre-scaled by 1/sqrt(64))
#pragma unroll
    for (int it = 0; it < 4; it++) {
        int idx = tid + it * 256;    // 0..1023
        int r   = idx >> 4;          // 0..63
        int c4  = idx & 15;          // 0..15
        float4 v = *(const float4*)(Qb + (size_t)(q0 + r) * D_MODEL + c4 * 4);
        Qst[(c4 * 4 + 0) * ROWW + r] = v.x * 0.125f;
        Qst[(c4 * 4 + 1) * ROWW + r] = v.y * 0.125f;
        Qst[(c4 * 4 + 2) * ROWW + r] = v.z * 0.125f;
        Qst[(c4 * 4 + 3) * ROWW + r] = v.w * 0.125f;
    }

    float o[4][4];
#pragma unroll
    for (int i = 0; i < 4; i++)
#pragma unroll
        for (int j = 0; j < 4; j++) o[i][j] = 0.0f;
    float mrow[4] = {-1e30f, -1e30f, -1e30f, -1e30f};
    float lrow[4] = {0.0f, 0.0f, 0.0f, 0.0f};

    for (int kt = 0; kt <= qt; kt++) {
        __syncthreads();   // previous iteration's consumers done
        // Load K (transposed) and V (row-major) tiles
#pragma unroll
        for (int it = 0; it < 4; it++) {
            int idx = tid + it * 256;
            int r   = idx >> 4;
            int c4  = idx & 15;
            float4 kv = *(const float4*)(Kb + (size_t)(kt * 64 + r) * D_MODEL + c4 * 4);
            Kst[(c4 * 4 + 0) * ROWW + r] = kv.x;
            Kst[(c4 * 4 + 1) * ROWW + r] = kv.y;
            Kst[(c4 * 4 + 2) * ROWW + r] = kv.z;
            Kst[(c4 * 4 + 3) * ROWW + r] = kv.w;
            float4 vv = *(const float4*)(Vb + (size_t)(kt * 64 + r) * D_MODEL + c4 * 4);
            *(float4*)(Vs + r * ROWW + c4 * 4) = vv;
        }
        __syncthreads();

        // S = Q @ K^T  (scaled already)
        float s[4][4];
#pragma unroll
        for (int i = 0; i < 4; i++)
#pragma unroll
            for (int j = 0; j < 4; j++) s[i][j] = 0.0f;
#pragma unroll
        for (int d = 0; d < 64; d++) {
            float4 a4 = *(const float4*)(Qst + d * ROWW + tr * 4);
            float4 b4 = *(const float4*)(Kst + d * ROWW + tc * 4);
            float av[4] = {a4.x, a4.y, a4.z, a4.w};
            float bv[4] = {b4.x, b4.y, b4.z, b4.w};
#pragma unroll
            for (int i = 0; i < 4; i++)
#pragma unroll
                for (int j = 0; j < 4; j++)
                    s[i][j] = fmaf(av[i], bv[j], s[i][j]);
        }

        // Causal mask (only diagonal tile)
        if (kt == qt) {
#pragma unroll
            for (int i = 0; i < 4; i++)
#pragma unroll
                for (int j = 0; j < 4; j++)
                    if (tc * 4 + j > tr * 4 + i) s[i][j] = -1e30f;
        }

        // Online softmax per row (16-lane half-warp reduction)
#pragma unroll
        for (int i = 0; i < 4; i++) {
            float mx = fmaxf(fmaxf(s[i][0], s[i][1]), fmaxf(s[i][2], s[i][3]));
#pragma unroll
            for (int off = 8; off >= 1; off >>= 1)
                mx = fmaxf(mx, __shfl_xor_sync(0xffffffffu, mx, off));
            float mnew = fmaxf(mrow[i], mx);
            float corr = __expf(mrow[i] - mnew);
            mrow[i] = mnew;
            float ps = 0.0f;
#pragma unroll
            for (int j = 0; j < 4; j++) {
                float p = __expf(s[i][j] - mnew);
                s[i][j] = p;
                ps += p;
            }
#pragma unroll
            for (int off = 8; off >= 1; off >>= 1)
                ps += __shfl_xor_sync(0xffffffffu, ps, off);
            lrow[i] = lrow[i] * corr + ps;
#pragma unroll
            for (int j = 0; j < 4; j++) o[i][j] *= corr;
        }

        // Write probabilities transposed: Pst[kj][qi]
#pragma unroll
        for (int j = 0; j < 4; j++)
            *(float4*)(Pst + (tc * 4 + j) * ROWW + tr * 4) =
                make_float4(s[0][j], s[1][j], s[2][j], s[3][j]);
        __syncthreads();

        // O += P @ V
#pragma unroll
        for (int kk = 0; kk < 64; kk++) {
            float4 p4 = *(const float4*)(Pst + kk * ROWW + tr * 4);
            float4 v4 = *(const float4*)(Vs + kk * ROWW + tc * 4);
            float pv[4] = {p4.x, p4.y, p4.z, p4.w};
            float vv[4] = {v4.x, v4.y, v4.z, v4.w};
#pragma unroll
            for (int i = 0; i < 4; i++)
#pragma unroll
                for (int j = 0; j < 4; j++)
                    o[i][j] = fmaf(pv[i], vv[j], o[i][j]);
        }
    }

    // Epilogue: normalize and store
    float* Ob = O + base;
#pragma unroll
    for (int i = 0; i < 4; i++) {
        float inv = 1.0f / lrow[i];
        *(float4*)(Ob + (size_t)(q0 + tr * 4 + i) * D_MODEL + tc * 4) =
            make_float4(o[i][0] * inv, o[i][1] * inv, o[i][2] * inv, o[i][3] * inv);
    }
}

// ---------------------------------------------------------------------------
// Launch
// ---------------------------------------------------------------------------
extern "C" void kernel_launch(void* const* d_in, const int* in_sizes, int n_in,
                              void* d_out, int out_size)
{
    (void)in_sizes; (void)n_in; (void)out_size;
    const float* x  = (const float*)d_in[0];
    const float* Wq = (const float*)d_in[1];
    const float* bq = (const float*)d_in[2];
    const float* Wk = (const float*)d_in[3];
    const float* bk = (const float*)d_in[4];
    const float* Wv = (const float*)d_in[5];
    const float* bv = (const float*)d_in[6];
    const float* Wo = (const float*)d_in[7];
    const float* bo = (const float*)d_in[8];
    float* out = (float*)d_out;

    float *qp, *kp, *vp, *op;
    cudaGetSymbolAddress((void**)&qp, g_Q);
    cudaGetSymbolAddress((void**)&kp, g_K);
    cudaGetSymbolAddress((void**)&vp, g_V);
    cudaGetSymbolAddress((void**)&op, g_O);

    const int smem_attn = 4 * 64 * ROWW * (int)sizeof(float);  // 69632 B
    static bool attr_set = false;
    if (!attr_set) {
        cudaFuncSetAttribute(attn_kernel,
                             cudaFuncAttributeMaxDynamicSharedMemorySize, smem_attn);
        attr_set = true;
    }

    dim3 gGemm(D_MODEL / BN, MTOT / BM);   // (8, 32)
    gemm_bias_kernel<<<gGemm, 256>>>(x, Wq, bq, qp, MTOT, D_MODEL, D_MODEL);
    gemm_bias_kernel<<<gGemm, 256>>>(x, Wk, bk, kp, MTOT, D_MODEL, D_MODEL);
    gemm_bias_kernel<<<gGemm, 256>>>(x, Wv, bv, vp, MTOT, D_MODEL, D_MODEL);

    dim3 gAttn(SEQ / 64, NHEAD, BATCH);    // (32, 16, 2)
    attn_kernel<<<gAttn, 256, smem_attn>>>(qp, kp, vp, op);

    gemm_bias_kernel<<<gGemm, 256>>>(op, Wo, bo, out, MTOT, D_MODEL, D_MODEL);
}

// round 3
// speedup vs baseline: 1.2847x; 1.2847x over previous
#include <cuda_runtime.h>
#include <cuda_bf16.h>
#include <cstdint>
#include <cstddef>

#define D_MODEL 1024
#define SEQ     2048
#define BATCH   2
#define NHEAD   16
#define HDIM    64
#define MTOT    (BATCH * SEQ)          // 4096 rows

// ---------------------------------------------------------------------------
// Scratch (no cudaMalloc allowed)
// ---------------------------------------------------------------------------
__device__ float g_Q[MTOT * D_MODEL];
__device__ float g_K[MTOT * D_MODEL];
__device__ float g_V[MTOT * D_MODEL];
__device__ float g_O[MTOT * D_MODEL];
__device__ __nv_bfloat16 g_xhi[MTOT * D_MODEL];
__device__ __nv_bfloat16 g_xlo[MTOT * D_MODEL];
__device__ __nv_bfloat16 g_whi[4 * D_MODEL * D_MODEL];
__device__ __nv_bfloat16 g_wlo[4 * D_MODEL * D_MODEL];
__device__ __nv_bfloat16 g_ohi[MTOT * D_MODEL];
__device__ __nv_bfloat16 g_olo[MTOT * D_MODEL];

// ---------------------------------------------------------------------------
// PTX helpers (sm_100-safe: no tcgen05, no 'a' features)
// ---------------------------------------------------------------------------
__device__ __forceinline__ uint32_t smem_u32(const void* p) {
    uint32_t a;
    asm("{ .reg .u64 t; cvta.to.shared.u64 t, %1; cvt.u32.u64 %0, t; }" : "=r"(a) : "l"(p));
    return a;
}
#define CP16(dst, src) \
    asm volatile("cp.async.cg.shared.global [%0], [%1], 16;" :: "r"(dst), "l"(src))
#define CP_COMMIT() asm volatile("cp.async.commit_group;" ::: "memory")
#define CP_WAIT(n)  asm volatile("cp.async.wait_group %0;" :: "n"(n) : "memory")

#define LDSM4(r0, r1, r2, r3, addr) \
    asm volatile("ldmatrix.sync.aligned.m8n8.x4.shared.b16 {%0,%1,%2,%3}, [%4];" \
                 : "=r"(r0), "=r"(r1), "=r"(r2), "=r"(r3) : "r"(addr))

#define MMA_BF16(d, a, b0, b1) \
    asm volatile("mma.sync.aligned.m16n8k16.row.col.f32.bf16.bf16.f32 " \
                 "{%0,%1,%2,%3}, {%4,%5,%6,%7}, {%8,%9}, {%0,%1,%2,%3};" \
                 : "+f"((d)[0]), "+f"((d)[1]), "+f"((d)[2]), "+f"((d)[3]) \
                 : "r"((a)[0]), "r"((a)[1]), "r"((a)[2]), "r"((a)[3]), \
                   "r"(b0), "r"(b1))

// ---------------------------------------------------------------------------
// fp32 -> bf16 hi/lo split
// ---------------------------------------------------------------------------
__global__ __launch_bounds__(256) void split_kernel(
    const float* __restrict__ src, __nv_bfloat16* __restrict__ hi,
    __nv_bfloat16* __restrict__ lo, int n4)
{
    int i = blockIdx.x * blockDim.x + threadIdx.x;
    if (i >= n4) return;
    float4 v = ((const float4*)src)[i];
    __nv_bfloat16 h0 = __float2bfloat16_rn(v.x);
    __nv_bfloat16 h1 = __float2bfloat16_rn(v.y);
    __nv_bfloat16 h2 = __float2bfloat16_rn(v.z);
    __nv_bfloat16 h3 = __float2bfloat16_rn(v.w);
    __nv_bfloat16 l0 = __float2bfloat16_rn(v.x - __bfloat162float(h0));
    __nv_bfloat16 l1 = __float2bfloat16_rn(v.y - __bfloat162float(h1));
    __nv_bfloat16 l2 = __float2bfloat16_rn(v.z - __bfloat162float(h2));
    __nv_bfloat16 l3 = __float2bfloat16_rn(v.w - __bfloat162float(h3));
    ((__nv_bfloat162*)hi)[2 * i]     = __nv_bfloat162(h0, h1);
    ((__nv_bfloat162*)hi)[2 * i + 1] = __nv_bfloat162(h2, h3);
    ((__nv_bfloat162*)lo)[2 * i]     = __nv_bfloat162(l0, l1);
    ((__nv_bfloat162*)lo)[2 * i + 1] = __nv_bfloat162(l2, l3);
}

// ---------------------------------------------------------------------------
// bf16 mma.sync GEMM: C[M,1024] = A[M,1024] @ W[1024,1024]^T + bias
// Split-as-K-extension: 96 chunks of BK=32 over sections
//   [0,32): Ah*Bh   [32,64): Ah*Bl   [64,96): Al*Bh
// 128x128 CTA tile, 8 warps (2M x 4N), 64x32 per warp, cp.async double buffer.
// Smem rows padded to 40 bf16 (80 B): ldmatrix phases conflict-free.
// ---------------------------------------------------------------------------
#define GK 1024
#define GN 1024
#define LDT 40

__global__ __launch_bounds__(256) void gemm_mma(
    const __nv_bfloat16* __restrict__ Ahi, const __nv_bfloat16* __restrict__ Alo,
    const __nv_bfloat16* __restrict__ Bhi, const __nv_bfloat16* __restrict__ Blo,
    const float* __restrict__ bias, float* __restrict__ C)
{
    __shared__ __align__(128) __nv_bfloat16 smA[2][128 * LDT];
    __shared__ __align__(128) __nv_bfloat16 smB[2][128 * LDT];

    const int tid = threadIdx.x;
    const int wid = tid >> 5;
    const int lane = tid & 31;
    const int bn = blockIdx.x * 128;
    const int bm = blockIdx.y * 128;
    const int wr = (wid & 1) * 64;     // warp M offset
    const int wc = (wid >> 1) * 32;    // warp N offset

    float acc[4][4][4];
#pragma unroll
    for (int mt = 0; mt < 4; mt++)
#pragma unroll
        for (int j = 0; j < 4; j++)
#pragma unroll
            for (int r = 0; r < 4; r++) acc[mt][j][r] = 0.0f;

    auto load_chunk = [&](int c, int stg) {
        const __nv_bfloat16* Ap = (c >= 64) ? Alo : Ahi;
        const __nv_bfloat16* Bp = (c >= 32 && c < 64) ? Blo : Bhi;
        const int k0 = (c & 31) * 32;
#pragma unroll
        for (int it = 0; it < 2; it++) {
            int idx = tid + it * 256;          // 0..511
            int r = idx >> 2, u = idx & 3;     // row, 16B unit
            uint32_t dst = smem_u32(&smA[stg][r * LDT]) + u * 16;
            CP16(dst, Ap + (size_t)(bm + r) * GK + k0 + u * 8);
        }
#pragma unroll
        for (int it = 0; it < 2; it++) {
            int idx = tid + it * 256;
            int r = idx >> 2, u = idx & 3;
            uint32_t dst = smem_u32(&smB[stg][r * LDT]) + u * 16;
            CP16(dst, Bp + (size_t)(bn + r) * GK + k0 + u * 8);
        }
    };

    auto compute = [&](int stg) {
#pragma unroll
        for (int ks = 0; ks < 2; ks++) {
            const int colb = ks * 32 + (lane >> 4) * 16;   // byte offset in row
            uint32_t a[4][4], b[2][4];
#pragma unroll
            for (int mt = 0; mt < 4; mt++) {
                uint32_t ad = smem_u32(&smA[stg][(wr + mt * 16 + (lane & 15)) * LDT]) + colb;
                LDSM4(a[mt][0], a[mt][1], a[mt][2], a[mt][3], ad);
            }
#pragma unroll
            for (int ng = 0; ng < 2; ng++) {
                uint32_t bd = smem_u32(&smB[stg][(wc + ng * 16 + (lane & 15)) * LDT]) + colb;
                LDSM4(b[ng][0], b[ng][1], b[ng][2], b[ng][3], bd);
            }
#pragma unroll
            for (int mt = 0; mt < 4; mt++)
#pragma unroll
                for (int j = 0; j < 4; j++)
                    MMA_BF16(acc[mt][j], a[mt], b[j >> 1][j & 1], b[j >> 1][(j & 1) + 2]);
        }
    };

    load_chunk(0, 0);
    CP_COMMIT();
    for (int c = 0; c < 96; c++) {
        const int cur = c & 1;
        if (c + 1 < 96) {
            load_chunk(c + 1, cur ^ 1);
            CP_COMMIT();
            CP_WAIT(1);
        } else {
            CP_WAIT(0);
        }
        __syncthreads();
        compute(cur);
        __syncthreads();
    }

    // Epilogue: add bias, write float2 pairs
    const int rq = lane >> 2;
    const int cq = (lane & 3) * 2;
#pragma unroll
    for (int mt = 0; mt < 4; mt++) {
#pragma unroll
        for (int j = 0; j < 4; j++) {
            const int col = bn + wc + j * 8 + cq;
            const float b0 = bias[col], b1 = bias[col + 1];
            const int row0 = bm + wr + mt * 16 + rq;
            *(float2*)(C + (size_t)row0 * GN + col) =
                make_float2(acc[mt][j][0] + b0, acc[mt][j][1] + b1);
            *(float2*)(C + (size_t)(row0 + 8) * GN + col) =
                make_float2(acc[mt][j][2] + b0, acc[mt][j][3] + b1);
        }
    }
}

// ---------------------------------------------------------------------------
// Flash attention (fp32, causal) — unchanged
// ---------------------------------------------------------------------------
#define ROWW 68

__global__ __launch_bounds__(256) void attn_kernel(
    const float* __restrict__ Q, const float* __restrict__ K,
    const float* __restrict__ V, float* __restrict__ O)
{
    extern __shared__ float smf[];
    float* Qst = smf;
    float* Kst = Qst + 64 * ROWW;
    float* Vs  = Kst + 64 * ROWW;
    float* Pst = Vs  + 64 * ROWW;

    const int qt = (int)gridDim.x - 1 - (int)blockIdx.x;
    const int h  = blockIdx.y;
    const int b  = blockIdx.z;
    const int tid = threadIdx.x;
    const int tr = tid >> 4;
    const int tc = tid & 15;
    const int q0 = qt * 64;

    const size_t base = (size_t)b * SEQ * D_MODEL + (size_t)h * HDIM;
    const float* Qb = Q + base;
    const float* Kb = K + base;
    const float* Vb = V + base;

#pragma unroll
    for (int it = 0; it < 4; it++) {
        int idx = tid + it * 256;
        int r   = idx >> 4;
        int c4  = idx & 15;
        float4 v = *(const float4*)(Qb + (size_t)(q0 + r) * D_MODEL + c4 * 4);
        Qst[(c4 * 4 + 0) * ROWW + r] = v.x * 0.125f;
        Qst[(c4 * 4 + 1) * ROWW + r] = v.y * 0.125f;
        Qst[(c4 * 4 + 2) * ROWW + r] = v.z * 0.125f;
        Qst[(c4 * 4 + 3) * ROWW + r] = v.w * 0.125f;
    }

    float o[4][4];
#pragma unroll
    for (int i = 0; i < 4; i++)
#pragma unroll
        for (int j = 0; j < 4; j++) o[i][j] = 0.0f;
    float mrow[4] = {-1e30f, -1e30f, -1e30f, -1e30f};
    float lrow[4] = {0.0f, 0.0f, 0.0f, 0.0f};

    for (int kt = 0; kt <= qt; kt++) {
        __syncthreads();
#pragma unroll
        for (int it = 0; it < 4; it++) {
            int idx = tid + it * 256;
            int r   = idx >> 4;
            int c4  = idx & 15;
            float4 kv = *(const float4*)(Kb + (size_t)(kt * 64 + r) * D_MODEL + c4 * 4);
            Kst[(c4 * 4 + 0) * ROWW + r] = kv.x;
            Kst[(c4 * 4 + 1) * ROWW + r] = kv.y;
            Kst[(c4 * 4 + 2) * ROWW + r] = kv.z;
            Kst[(c4 * 4 + 3) * ROWW + r] = kv.w;
            float4 vv = *(const float4*)(Vb + (size_t)(kt * 64 + r) * D_MODEL + c4 * 4);
            *(float4*)(Vs + r * ROWW + c4 * 4) = vv;
        }
        __syncthreads();

        float s[4][4];
#pragma unroll
        for (int i = 0; i < 4; i++)
#pragma unroll
            for (int j = 0; j < 4; j++) s[i][j] = 0.0f;
#pragma unroll
        for (int d = 0; d < 64; d++) {
            float4 a4 = *(const float4*)(Qst + d * ROWW + tr * 4);
            float4 b4 = *(const float4*)(Kst + d * ROWW + tc * 4);
            float av[4] = {a4.x, a4.y, a4.z, a4.w};
            float bv[4] = {b4.x, b4.y, b4.z, b4.w};
#pragma unroll
            for (int i = 0; i < 4; i++)
#pragma unroll
                for (int j = 0; j < 4; j++)
                    s[i][j] = fmaf(av[i], bv[j], s[i][j]);
        }

        if (kt == qt) {
#pragma unroll
            for (int i = 0; i < 4; i++)
#pragma unroll
                for (int j = 0; j < 4; j++)
                    if (tc * 4 + j > tr * 4 + i) s[i][j] = -1e30f;
        }

#pragma unroll
        for (int i = 0; i < 4; i++) {
            float mx = fmaxf(fmaxf(s[i][0], s[i][1]), fmaxf(s[i][2], s[i][3]));
#pragma unroll
            for (int off = 8; off >= 1; off >>= 1)
                mx = fmaxf(mx, __shfl_xor_sync(0xffffffffu, mx, off));
            float mnew = fmaxf(mrow[i], mx);
            float corr = __expf(mrow[i] - mnew);
            mrow[i] = mnew;
            float ps = 0.0f;
#pragma unroll
            for (int j = 0; j < 4; j++) {
                float p = __expf(s[i][j] - mnew);
                s[i][j] = p;
                ps += p;
            }
#pragma unroll
            for (int off = 8; off >= 1; off >>= 1)
                ps += __shfl_xor_sync(0xffffffffu, ps, off);
            lrow[i] = lrow[i] * corr + ps;
#pragma unroll
            for (int j = 0; j < 4; j++) o[i][j] *= corr;
        }

#pragma unroll
        for (int j = 0; j < 4; j++)
            *(float4*)(Pst + (tc * 4 + j) * ROWW + tr * 4) =
                make_float4(s[0][j], s[1][j], s[2][j], s[3][j]);
        __syncthreads();

#pragma unroll
        for (int kk = 0; kk < 64; kk++) {
            float4 p4 = *(const float4*)(Pst + kk * ROWW + tr * 4);
            float4 v4 = *(const float4*)(Vs + kk * ROWW + tc * 4);
            float pv[4] = {p4.x, p4.y, p4.z, p4.w};
            float vv[4] = {v4.x, v4.y, v4.z, v4.w};
#pragma unroll
            for (int i = 0; i < 4; i++)
#pragma unroll
                for (int j = 0; j < 4; j++)
                    o[i][j] = fmaf(pv[i], vv[j], o[i][j]);
        }
    }

    float* Ob = O + base;
#pragma unroll
    for (int i = 0; i < 4; i++) {
        float inv = 1.0f / lrow[i];
        *(float4*)(Ob + (size_t)(q0 + tr * 4 + i) * D_MODEL + tc * 4) =
            make_float4(o[i][0] * inv, o[i][1] * inv, o[i][2] * inv, o[i][3] * inv);
    }
}

// ---------------------------------------------------------------------------
// Launch
// ---------------------------------------------------------------------------
extern "C" void kernel_launch(void* const* d_in, const int* in_sizes, int n_in,
                              void* d_out, int out_size)
{
    (void)in_sizes; (void)n_in; (void)out_size;
    const float* x  = (const float*)d_in[0];
    const float* Wq = (const float*)d_in[1];
    const float* bq = (const float*)d_in[2];
    const float* Wk = (const float*)d_in[3];
    const float* bk = (const float*)d_in[4];
    const float* Wv = (const float*)d_in[5];
    const float* bv = (const float*)d_in[6];
    const float* Wo = (const float*)d_in[7];
    const float* bo = (const float*)d_in[8];
    float* out = (float*)d_out;

    float *qp, *kp, *vp, *op;
    __nv_bfloat16 *xhi, *xlo, *whi, *wlo, *ohi, *olo;
    cudaGetSymbolAddress((void**)&qp, g_Q);
    cudaGetSymbolAddress((void**)&kp, g_K);
    cudaGetSymbolAddress((void**)&vp, g_V);
    cudaGetSymbolAddress((void**)&op, g_O);
    cudaGetSymbolAddress((void**)&xhi, g_xhi);
    cudaGetSymbolAddress((void**)&xlo, g_xlo);
    cudaGetSymbolAddress((void**)&whi, g_whi);
    cudaGetSymbolAddress((void**)&wlo, g_wlo);
    cudaGetSymbolAddress((void**)&ohi, g_ohi);
    cudaGetSymbolAddress((void**)&olo, g_olo);

    const int smem_attn = 4 * 64 * ROWW * (int)sizeof(float);  // 69632 B
    cudaFuncSetAttribute(attn_kernel,
                         cudaFuncAttributeMaxDynamicSharedMemorySize, smem_attn);

    const int WN = D_MODEL * D_MODEL;
    const int n4x = MTOT * D_MODEL / 4;
    const int n4w = WN / 4;

    split_kernel<<<(n4x + 255) / 256, 256>>>(x, xhi, xlo, n4x);
    split_kernel<<<(n4w + 255) / 256, 256>>>(Wq, whi + 0 * WN, wlo + 0 * WN, n4w);
    split_kernel<<<(n4w + 255) / 256, 256>>>(Wk, whi + 1 * WN, wlo + 1 * WN, n4w);
    split_kernel<<<(n4w + 255) / 256, 256>>>(Wv, whi + 2 * WN, wlo + 2 * WN, n4w);
    split_kernel<<<(n4w + 255) / 256, 256>>>(Wo, whi + 3 * WN, wlo + 3 * WN, n4w);

    dim3 gGemm(GN / 128, MTOT / 128);          // (8, 32)
    gemm_mma<<<gGemm, 256>>>(xhi, xlo, whi + 0 * WN, wlo + 0 * WN, bq, qp);
    gemm_mma<<<gGemm, 256>>>(xhi, xlo, whi + 1 * WN, wlo + 1 * WN, bk, kp);
    gemm_mma<<<gGemm, 256>>>(xhi, xlo, whi + 2 * WN, wlo + 2 * WN, bv, vp);

    dim3 gAttn(SEQ / 64, NHEAD, BATCH);        // (32, 16, 2)
    attn_kernel<<<gAttn, 256, smem_attn>>>(qp, kp, vp, op);

    split_kernel<<<(n4x + 255) / 256, 256>>>(op, ohi, olo, n4x);
    gemm_mma<<<gGemm, 256>>>(ohi, olo, whi + 3 * WN, wlo + 3 * WN, bo, out);
}

// round 4
// speedup vs baseline: 2.0330x; 1.5825x over previous
#include <cuda_runtime.h>
#include <cuda_bf16.h>
#include <cstdint>
#include <cstddef>

#define D_MODEL 1024
#define SEQ     2048
#define BATCH   2
#define NHEAD   16
#define HDIM    64
#define MTOT    (BATCH * SEQ)          // 4096 rows

// ---------------------------------------------------------------------------
// Scratch (no cudaMalloc allowed) — all bf16 hi/lo pairs
// ---------------------------------------------------------------------------
__device__ __nv_bfloat16 g_xhi[MTOT * D_MODEL];
__device__ __nv_bfloat16 g_xlo[MTOT * D_MODEL];
__device__ __nv_bfloat16 g_whi[4 * D_MODEL * D_MODEL];
__device__ __nv_bfloat16 g_wlo[4 * D_MODEL * D_MODEL];
__device__ __nv_bfloat16 g_qhi[MTOT * D_MODEL];
__device__ __nv_bfloat16 g_qlo[MTOT * D_MODEL];
__device__ __nv_bfloat16 g_khi[MTOT * D_MODEL];
__device__ __nv_bfloat16 g_klo[MTOT * D_MODEL];
__device__ __nv_bfloat16 g_vhi[MTOT * D_MODEL];
__device__ __nv_bfloat16 g_vlo[MTOT * D_MODEL];
__device__ __nv_bfloat16 g_ohi[MTOT * D_MODEL];
__device__ __nv_bfloat16 g_olo[MTOT * D_MODEL];

// ---------------------------------------------------------------------------
// PTX helpers (sm_100-safe)
// ---------------------------------------------------------------------------
__device__ __forceinline__ uint32_t smem_u32(const void* p) {
    uint32_t a;
    asm("{ .reg .u64 t; cvta.to.shared.u64 t, %1; cvt.u32.u64 %0, t; }" : "=r"(a) : "l"(p));
    return a;
}
#define CP16(dst, src) \
    asm volatile("cp.async.cg.shared.global [%0], [%1], 16;" :: "r"(dst), "l"(src))
#define CP_COMMIT() asm volatile("cp.async.commit_group;" ::: "memory")
#define CP_WAIT(n)  asm volatile("cp.async.wait_group %0;" :: "n"(n) : "memory")

#define LDSM4(r0, r1, r2, r3, addr) \
    asm volatile("ldmatrix.sync.aligned.m8n8.x4.shared.b16 {%0,%1,%2,%3}, [%4];" \
                 : "=r"(r0), "=r"(r1), "=r"(r2), "=r"(r3) : "r"(addr))
#define LDSM4T(r0, r1, r2, r3, addr) \
    asm volatile("ldmatrix.sync.aligned.m8n8.x4.trans.shared.b16 {%0,%1,%2,%3}, [%4];" \
                 : "=r"(r0), "=r"(r1), "=r"(r2), "=r"(r3) : "r"(addr))

#define MMA_BF16(d, a, b0, b1) \
    asm volatile("mma.sync.aligned.m16n8k16.row.col.f32.bf16.bf16.f32 " \
                 "{%0,%1,%2,%3}, {%4,%5,%6,%7}, {%8,%9}, {%0,%1,%2,%3};" \
                 : "+f"((d)[0]), "+f"((d)[1]), "+f"((d)[2]), "+f"((d)[3]) \
                 : "r"((a)[0]), "r"((a)[1]), "r"((a)[2]), "r"((a)[3]), \
                   "r"(b0), "r"(b1))

// pack two fp32 into bf16 hi pair + bf16 residual pair
__device__ __forceinline__ void split2(float a, float b, uint32_t& hi, uint32_t& lo) {
    __nv_bfloat162 h = __floats2bfloat162_rn(a, b);
    float ra = a - __bfloat162float(h.x);
    float rb = b - __bfloat162float(h.y);
    __nv_bfloat162 l = __floats2bfloat162_rn(ra, rb);
    hi = *(uint32_t*)&h;
    lo = *(uint32_t*)&l;
}

// ---------------------------------------------------------------------------
// fp32 -> bf16 hi/lo split (bulk, for x and weights)
// ---------------------------------------------------------------------------
__global__ __launch_bounds__(256) void split_kernel(
    const float* __restrict__ src, __nv_bfloat16* __restrict__ hi,
    __nv_bfloat16* __restrict__ lo, int n4)
{
    int i = blockIdx.x * blockDim.x + threadIdx.x;
    if (i >= n4) return;
    float4 v = ((const float4*)src)[i];
    uint32_t h0, l0, h1, l1;
    split2(v.x, v.y, h0, l0);
    split2(v.z, v.w, h1, l1);
    ((uint32_t*)hi)[2 * i] = h0;  ((uint32_t*)hi)[2 * i + 1] = h1;
    ((uint32_t*)lo)[2 * i] = l0;  ((uint32_t*)lo)[2 * i + 1] = l1;
}

// ---------------------------------------------------------------------------
// bf16 mma.sync GEMM, split-as-K-extension (96 chunks of BK=32).
// SPLIT_OUT: write bf16 hi/lo instead of fp32.
// ---------------------------------------------------------------------------
#define GK 1024
#define GN 1024
#define LDT 40

template <bool SPLIT_OUT>
__global__ __launch_bounds__(256) void gemm_mma(
    const __nv_bfloat16* __restrict__ Ahi, const __nv_bfloat16* __restrict__ Alo,
    const __nv_bfloat16* __restrict__ Bhi, const __nv_bfloat16* __restrict__ Blo,
    const float* __restrict__ bias, float* __restrict__ C,
    __nv_bfloat16* __restrict__ Chi, __nv_bfloat16* __restrict__ Clo)
{
    __shared__ __align__(128) __nv_bfloat16 smA[2][128 * LDT];
    __shared__ __align__(128) __nv_bfloat16 smB[2][128 * LDT];

    const int tid = threadIdx.x;
    const int wid = tid >> 5;
    const int lane = tid & 31;
    const int bn = blockIdx.x * 128;
    const int bm = blockIdx.y * 128;
    const int wr = (wid & 1) * 64;
    const int wc = (wid >> 1) * 32;

    float acc[4][4][4];
#pragma unroll
    for (int mt = 0; mt < 4; mt++)
#pragma unroll
        for (int j = 0; j < 4; j++)
#pragma unroll
            for (int r = 0; r < 4; r++) acc[mt][j][r] = 0.0f;

    auto load_chunk = [&](int c, int stg) {
        const __nv_bfloat16* Ap = (c >= 64) ? Alo : Ahi;
        const __nv_bfloat16* Bp = (c >= 32 && c < 64) ? Blo : Bhi;
        const int k0 = (c & 31) * 32;
#pragma unroll
        for (int it = 0; it < 2; it++) {
            int idx = tid + it * 256;
            int r = idx >> 2, u = idx & 3;
            CP16(smem_u32(&smA[stg][r * LDT]) + u * 16, Ap + (size_t)(bm + r) * GK + k0 + u * 8);
        }
#pragma unroll
        for (int it = 0; it < 2; it++) {
            int idx = tid + it * 256;
            int r = idx >> 2, u = idx & 3;
            CP16(smem_u32(&smB[stg][r * LDT]) + u * 16, Bp + (size_t)(bn + r) * GK + k0 + u * 8);
        }
    };

    auto compute = [&](int stg) {
#pragma unroll
        for (int ks = 0; ks < 2; ks++) {
            const int colb = ks * 32 + (lane >> 4) * 16;
            uint32_t a[4][4], b[2][4];
#pragma unroll
            for (int mt = 0; mt < 4; mt++) {
                uint32_t ad = smem_u32(&smA[stg][(wr + mt * 16 + (lane & 15)) * LDT]) + colb;
                LDSM4(a[mt][0], a[mt][1], a[mt][2], a[mt][3], ad);
            }
#pragma unroll
            for (int ng = 0; ng < 2; ng++) {
                uint32_t bd = smem_u32(&smB[stg][(wc + ng * 16 + (lane & 15)) * LDT]) + colb;
                LDSM4(b[ng][0], b[ng][1], b[ng][2], b[ng][3], bd);
            }
#pragma unroll
            for (int mt = 0; mt < 4; mt++)
#pragma unroll
                for (int j = 0; j < 4; j++)
                    MMA_BF16(acc[mt][j], a[mt], b[j >> 1][j & 1], b[j >> 1][(j & 1) + 2]);
        }
    };

    load_chunk(0, 0);
    CP_COMMIT();
    for (int c = 0; c < 96; c++) {
        const int cur = c & 1;
        if (c + 1 < 96) {
            load_chunk(c + 1, cur ^ 1);
            CP_COMMIT();
            CP_WAIT(1);
        } else {
            CP_WAIT(0);
        }
        __syncthreads();
        compute(cur);
        __syncthreads();
    }

    const int rq = lane >> 2;
    const int cq = (lane & 3) * 2;
#pragma unroll
    for (int mt = 0; mt < 4; mt++) {
#pragma unroll
        for (int j = 0; j < 4; j++) {
            const int col = bn + wc + j * 8 + cq;
            const float b0 = bias[col], b1 = bias[col + 1];
            const int row0 = bm + wr + mt * 16 + rq;
            float v0 = acc[mt][j][0] + b0, v1 = acc[mt][j][1] + b1;
            float v2 = acc[mt][j][2] + b0, v3 = acc[mt][j][3] + b1;
            if (SPLIT_OUT) {
                uint32_t h01, l01;
                split2(v0, v1, h01, l01);
                *(uint32_t*)(Chi + (size_t)row0 * GN + col) = h01;
                *(uint32_t*)(Clo + (size_t)row0 * GN + col) = l01;
                split2(v2, v3, h01, l01);
                *(uint32_t*)(Chi + (size_t)(row0 + 8) * GN + col) = h01;
                *(uint32_t*)(Clo + (size_t)(row0 + 8) * GN + col) = l01;
            } else {
                *(float2*)(C + (size_t)row0 * GN + col) = make_float2(v0, v1);
                *(float2*)(C + (size_t)(row0 + 8) * GN + col) = make_float2(v2, v3);
            }
        }
    }
}

// ---------------------------------------------------------------------------
// Flash attention, bf16 mma.sync, causal.
// CTA: 128 Q rows x one (b,h); 8 warps x 16 rows. KT = 64 keys/iter,
// double-buffered cp.async K/V (hi+lo). fp32 online softmax in registers.
// S = QhKh + QlKh + QhKl;  PV = PhVh + PlVh + PhVl.
// ---------------------------------------------------------------------------
#define ALD 72                         // smem row stride in bf16 (144 B)
#define AQ_B  (128 * ALD * 2)          // 18432 B per Q matrix
#define AM_B  (64 * ALD * 2)           // 9216 B per K/V matrix
#define AST_B (4 * AM_B)               // stage: Kh,Kl,Vh,Vl = 36864 B
#define ATTN_SMEM (2 * AQ_B + 2 * AST_B)   // 110592 B

__global__ __launch_bounds__(256) void attn_mma(
    const __nv_bfloat16* __restrict__ Qhi, const __nv_bfloat16* __restrict__ Qlo,
    const __nv_bfloat16* __restrict__ Khi, const __nv_bfloat16* __restrict__ Klo,
    const __nv_bfloat16* __restrict__ Vhi, const __nv_bfloat16* __restrict__ Vlo,
    __nv_bfloat16* __restrict__ Ohi, __nv_bfloat16* __restrict__ Olo)
{
    extern __shared__ __align__(128) char smc[];
    const uint32_t smb = smem_u32(smc);
    const int tid = threadIdx.x;
    const int wid = tid >> 5;
    const int lane = tid & 31;
    const int qt = (int)gridDim.x - 1 - (int)blockIdx.x;   // long tiles first
    const int h = blockIdx.y, b = blockIdx.z;
    const int q0 = qt * 128;
    const size_t rc0 = (size_t)b * SEQ * D_MODEL + h * HDIM;

    const int wr = wid * 16;
    const uint32_t lrow = lane & 15;
    const uint32_t lc16 = (lane >> 4) * 16;

    auto load_q = [&] {
#pragma unroll
        for (int it = 0; it < 8; it++) {
            int t = tid + it * 256;                 // 0..2047
            const __nv_bfloat16* src = (t < 1024) ? Qhi : Qlo;
            uint32_t moff = (t < 1024) ? 0u : (uint32_t)AQ_B;
            int idx = t & 1023, r = idx >> 3, u = idx & 7;
            CP16(smb + moff + (uint32_t)(r * ALD + u * 8) * 2,
                 src + rc0 + (size_t)(q0 + r) * D_MODEL + u * 8);
        }
    };
    auto load_kv = [&](int kt, int stg) {
        const uint32_t sb = smb + 2 * AQ_B + stg * AST_B;
#pragma unroll
        for (int it = 0; it < 8; it++) {
            int t = tid + it * 256;                 // 0..2047
            int mtx = t >> 9;                       // 0:Kh 1:Kl 2:Vh 3:Vl
            int idx = t & 511, r = idx >> 3, u = idx & 7;
            const __nv_bfloat16* src = (mtx == 0) ? Khi : (mtx == 1) ? Klo
                                      : (mtx == 2) ? Vhi : Vlo;
            CP16(sb + mtx * AM_B + (uint32_t)(r * ALD + u * 8) * 2,
                 src + rc0 + (size_t)(kt * 64 + r) * D_MODEL + u * 8);
        }
    };

    float o[8][4];
#pragma unroll
    for (int nt = 0; nt < 8; nt++)
#pragma unroll
        for (int c = 0; c < 4; c++) o[nt][c] = 0.0f;
    float m0 = -1e30f, m1 = -1e30f, l0 = 0.0f, l1 = 0.0f;
    uint32_t qh[4][4], ql[4][4];

    load_q();
    load_kv(0, 0);
    CP_COMMIT();

    const int ktEnd = 2 * qt + 2;
    for (int kt = 0; kt < ktEnd; kt++) {
        if (kt + 1 < ktEnd) {
            load_kv(kt + 1, (kt + 1) & 1);
            CP_COMMIT();
            CP_WAIT(1);
        } else {
            CP_WAIT(0);
        }
        __syncthreads();

        if (kt == 0) {
#pragma unroll
            for (int ks = 0; ks < 4; ks++) {
                uint32_t a1 = smb + (uint32_t)((wr + lrow) * ALD) * 2 + ks * 32 + lc16;
                LDSM4(qh[ks][0], qh[ks][1], qh[ks][2], qh[ks][3], a1);
                LDSM4(ql[ks][0], ql[ks][1], ql[ks][2], ql[ks][3], a1 + AQ_B);
            }
        }

        const uint32_t sb = smb + 2 * AQ_B + (kt & 1) * AST_B;

        // ---- S = Q K^T (3 split terms) ----
        float s[8][4];
#pragma unroll
        for (int nt = 0; nt < 8; nt++)
#pragma unroll
            for (int c = 0; c < 4; c++) s[nt][c] = 0.0f;

#pragma unroll
        for (int ks = 0; ks < 4; ks++) {
            uint32_t kf[4][4];
#pragma unroll
            for (int ng = 0; ng < 4; ng++) {
                uint32_t a1 = sb + (uint32_t)((ng * 16 + lrow) * ALD) * 2 + ks * 32 + lc16;
                LDSM4(kf[ng][0], kf[ng][1], kf[ng][2], kf[ng][3], a1);
            }
#pragma unroll
            for (int nt = 0; nt < 8; nt++) {
                MMA_BF16(s[nt], qh[ks], kf[nt >> 1][nt & 1], kf[nt >> 1][(nt & 1) + 2]);
                MMA_BF16(s[nt], ql[ks], kf[nt >> 1][nt & 1], kf[nt >> 1][(nt & 1) + 2]);
            }
#pragma unroll
            for (int ng = 0; ng < 4; ng++) {
                uint32_t a1 = sb + AM_B + (uint32_t)((ng * 16 + lrow) * ALD) * 2 + ks * 32 + lc16;
                LDSM4(kf[ng][0], kf[ng][1], kf[ng][2], kf[ng][3], a1);
            }
#pragma unroll
            for (int nt = 0; nt < 8; nt++)
                MMA_BF16(s[nt], qh[ks], kf[nt >> 1][nt & 1], kf[nt >> 1][(nt & 1) + 2]);
        }

#pragma unroll
        for (int nt = 0; nt < 8; nt++)
#pragma unroll
            for (int c = 0; c < 4; c++) s[nt][c] *= 0.125f;

        // ---- causal mask (diagonal tiles only) ----
        if (kt * 64 + 63 > q0 + wr) {
            const int r0 = q0 + wr + (lane >> 2);
#pragma unroll
            for (int nt = 0; nt < 8; nt++) {
                const int c0 = kt * 64 + nt * 8 + 2 * (lane & 3);
                if (c0 > r0)         s[nt][0] = -1e30f;
                if (c0 + 1 > r0)     s[nt][1] = -1e30f;
                if (c0 > r0 + 8)     s[nt][2] = -1e30f;
                if (c0 + 1 > r0 + 8) s[nt][3] = -1e30f;
            }
        }

        // ---- online softmax (fp32, per row-half, quad shuffles) ----
        float mx0 = -1e30f, mx1 = -1e30f;
#pragma unroll
        for (int nt = 0; nt < 8; nt++) {
            mx0 = fmaxf(mx0, fmaxf(s[nt][0], s[nt][1]));
            mx1 = fmaxf(mx1, fmaxf(s[nt][2], s[nt][3]));
        }
        mx0 = fmaxf(mx0, __shfl_xor_sync(0xffffffffu, mx0, 1));
        mx0 = fmaxf(mx0, __shfl_xor_sync(0xffffffffu, mx0, 2));
        mx1 = fmaxf(mx1, __shfl_xor_sync(0xffffffffu, mx1, 1));
        mx1 = fmaxf(mx1, __shfl_xor_sync(0xffffffffu, mx1, 2));
        const float n0 = fmaxf(m0, mx0), n1 = fmaxf(m1, mx1);
        const float cr0 = __expf(m0 - n0), cr1 = __expf(m1 - n1);
        m0 = n0; m1 = n1;
        float sum0 = 0.0f, sum1 = 0.0f;
#pragma unroll
        for (int nt = 0; nt < 8; nt++) {
            s[nt][0] = __expf(s[nt][0] - n0); sum0 += s[nt][0];
            s[nt][1] = __expf(s[nt][1] - n0); sum0 += s[nt][1];
            s[nt][2] = __expf(s[nt][2] - n1); sum1 += s[nt][2];
            s[nt][3] = __expf(s[nt][3] - n1); sum1 += s[nt][3];
        }
        sum0 += __shfl_xor_sync(0xffffffffu, sum0, 1);
        sum0 += __shfl_xor_sync(0xffffffffu, sum0, 2);
        sum1 += __shfl_xor_sync(0xffffffffu, sum1, 1);
        sum1 += __shfl_xor_sync(0xffffffffu, sum1, 2);
        l0 = l0 * cr0 + sum0;
        l1 = l1 * cr1 + sum1;
#pragma unroll
        for (int nt = 0; nt < 8; nt++) {
            o[nt][0] *= cr0; o[nt][1] *= cr0;
            o[nt][2] *= cr1; o[nt][3] *= cr1;
        }

        // ---- P fragments (bf16 hi + residual) ----
        uint32_t ph[4][4], pl[4][4];
#pragma unroll
        for (int ks = 0; ks < 4; ks++) {
            split2(s[2 * ks][0], s[2 * ks][1], ph[ks][0], pl[ks][0]);
            split2(s[2 * ks][2], s[2 * ks][3], ph[ks][1], pl[ks][1]);
            split2(s[2 * ks + 1][0], s[2 * ks + 1][1], ph[ks][2], pl[ks][2]);
            split2(s[2 * ks + 1][2], s[2 * ks + 1][3], ph[ks][3], pl[ks][3]);
        }

        // ---- O += P V (3 split terms) ----
#pragma unroll
        for (int ks = 0; ks < 4; ks++) {
            uint32_t vh[4][4], vl[4][4];
#pragma unroll
            for (int ng = 0; ng < 4; ng++) {
                uint32_t a1 = sb + 2 * AM_B + (uint32_t)((ks * 16 + lrow) * ALD) * 2 + ng * 32 + lc16;
                LDSM4T(vh[ng][0], vh[ng][1], vh[ng][2], vh[ng][3], a1);
                LDSM4T(vl[ng][0], vl[ng][1], vl[ng][2], vl[ng][3], a1 + AM_B);
            }
#pragma unroll
            for (int nt = 0; nt < 8; nt++) {
                const uint32_t b0 = vh[nt >> 1][(nt & 1) * 2];
                const uint32_t b1 = vh[nt >> 1][(nt & 1) * 2 + 1];
                MMA_BF16(o[nt], ph[ks], b0, b1);
                MMA_BF16(o[nt], pl[ks], b0, b1);
                MMA_BF16(o[nt], ph[ks], vl[nt >> 1][(nt & 1) * 2], vl[nt >> 1][(nt & 1) * 2 + 1]);
            }
        }
        __syncthreads();
    }

    // ---- epilogue: normalize, split to bf16 hi/lo ----
    const float i0 = 1.0f / l0, i1 = 1.0f / l1;
    const size_t r0 = (size_t)(b * SEQ + q0 + wr + (lane >> 2));
    const int colb = h * HDIM + 2 * (lane & 3);
#pragma unroll
    for (int nt = 0; nt < 8; nt++) {
        const int col = colb + nt * 8;
        uint32_t h01, l01;
        split2(o[nt][0] * i0, o[nt][1] * i0, h01, l01);
        *(uint32_t*)(Ohi + r0 * D_MODEL + col) = h01;
        *(uint32_t*)(Olo + r0 * D_MODEL + col) = l01;
        split2(o[nt][2] * i1, o[nt][3] * i1, h01, l01);
        *(uint32_t*)(Ohi + (r0 + 8) * D_MODEL + col) = h01;
        *(uint32_t*)(Olo + (r0 + 8) * D_MODEL + col) = l01;
    }
}

// ---------------------------------------------------------------------------
// Launch
// ---------------------------------------------------------------------------
extern "C" void kernel_launch(void* const* d_in, const int* in_sizes, int n_in,
                              void* d_out, int out_size)
{
    (void)in_sizes; (void)n_in; (void)out_size;
    const float* x  = (const float*)d_in[0];
    const float* Wq = (const float*)d_in[1];
    const float* bq = (const float*)d_in[2];
    const float* Wk = (const float*)d_in[3];
    const float* bk = (const float*)d_in[4];
    const float* Wv = (const float*)d_in[5];
    const float* bv = (const float*)d_in[6];
    const float* Wo = (const float*)d_in[7];
    const float* bo = (const float*)d_in[8];
    float* out = (float*)d_out;

    __nv_bfloat16 *xhi, *xlo, *whi, *wlo;
    __nv_bfloat16 *qhi, *qlo, *khi, *klo, *vhi, *vlo, *ohi, *olo;
    cudaGetSymbolAddress((void**)&xhi, g_xhi);
    cudaGetSymbolAddress((void**)&xlo, g_xlo);
    cudaGetSymbolAddress((void**)&whi, g_whi);
    cudaGetSymbolAddress((void**)&wlo, g_wlo);
    cudaGetSymbolAddress((void**)&qhi, g_qhi);
    cudaGetSymbolAddress((void**)&qlo, g_qlo);
    cudaGetSymbolAddress((void**)&khi, g_khi);
    cudaGetSymbolAddress((void**)&klo, g_klo);
    cudaGetSymbolAddress((void**)&vhi, g_vhi);
    cudaGetSymbolAddress((void**)&vlo, g_vlo);
    cudaGetSymbolAddress((void**)&ohi, g_ohi);
    cudaGetSymbolAddress((void**)&olo, g_olo);

    cudaFuncSetAttribute(attn_mma,
                         cudaFuncAttributeMaxDynamicSharedMemorySize, ATTN_SMEM);

    const int WN = D_MODEL * D_MODEL;
    const int n4x = MTOT * D_MODEL / 4;
    const int n4w = WN / 4;

    split_kernel<<<(n4x + 255) / 256, 256>>>(x, xhi, xlo, n4x);
    split_kernel<<<(n4w + 255) / 256, 256>>>(Wq, whi + 0 * WN, wlo + 0 * WN, n4w);
    split_kernel<<<(n4w + 255) / 256, 256>>>(Wk, whi + 1 * WN, wlo + 1 * WN, n4w);
    split_kernel<<<(n4w + 255) / 256, 256>>>(Wv, whi + 2 * WN, wlo + 2 * WN, n4w);
    split_kernel<<<(n4w + 255) / 256, 256>>>(Wo, whi + 3 * WN, wlo + 3 * WN, n4w);

    dim3 gGemm(GN / 128, MTOT / 128);          // (8, 32)
    gemm_mma<true><<<gGemm, 256>>>(xhi, xlo, whi + 0 * WN, wlo + 0 * WN, bq,
                                   nullptr, qhi, qlo);
    gemm_mma<true><<<gGemm, 256>>>(xhi, xlo, whi + 1 * WN, wlo + 1 * WN, bk,
                                   nullptr, khi, klo);
    gemm_mma<true><<<gGemm, 256>>>(xhi, xlo, whi + 2 * WN, wlo + 2 * WN, bv,
                                   nullptr, vhi, vlo);

    dim3 gAttn(SEQ / 128, NHEAD, BATCH);       // (16, 16, 2)
    attn_mma<<<gAttn, 256, ATTN_SMEM>>>(qhi, qlo, khi, klo, vhi, vlo, ohi, olo);

    gemm_mma<false><<<gGemm, 256>>>(ohi, olo, whi + 3 * WN, wlo + 3 * WN, bo,
                                    out, nullptr, nullptr);
}

// round 5
// speedup vs baseline: 2.1527x; 1.0589x over previous
#include <cuda_runtime.h>
#include <cuda_bf16.h>
#include <cstdint>
#include <cstddef>

#define D_MODEL 1024
#define SEQ     2048
#define BATCH   2
#define NHEAD   16
#define HDIM    64
#define MTOT    (BATCH * SEQ)          // 4096 rows

// ---------------------------------------------------------------------------
// Scratch (no cudaMalloc allowed) — all bf16 hi/lo pairs
// ---------------------------------------------------------------------------
__device__ __nv_bfloat16 g_xhi[MTOT * D_MODEL];
__device__ __nv_bfloat16 g_xlo[MTOT * D_MODEL];
__device__ __nv_bfloat16 g_whi[4 * D_MODEL * D_MODEL];
__device__ __nv_bfloat16 g_wlo[4 * D_MODEL * D_MODEL];
__device__ __nv_bfloat16 g_qhi[MTOT * D_MODEL];
__device__ __nv_bfloat16 g_qlo[MTOT * D_MODEL];
__device__ __nv_bfloat16 g_khi[MTOT * D_MODEL];
__device__ __nv_bfloat16 g_klo[MTOT * D_MODEL];
__device__ __nv_bfloat16 g_vhi[MTOT * D_MODEL];
__device__ __nv_bfloat16 g_vlo[MTOT * D_MODEL];
__device__ __nv_bfloat16 g_ohi[MTOT * D_MODEL];
__device__ __nv_bfloat16 g_olo[MTOT * D_MODEL];

// ---------------------------------------------------------------------------
// PTX helpers (sm_100-safe)
// ---------------------------------------------------------------------------
__device__ __forceinline__ uint32_t smem_u32(const void* p) {
    uint32_t a;
    asm("{ .reg .u64 t; cvta.to.shared.u64 t, %1; cvt.u32.u64 %0, t; }" : "=r"(a) : "l"(p));
    return a;
}
#define CP16(dst, src) \
    asm volatile("cp.async.cg.shared.global [%0], [%1], 16;" :: "r"(dst), "l"(src))
#define CP_COMMIT() asm volatile("cp.async.commit_group;" ::: "memory")
#define CP_WAIT(n)  asm volatile("cp.async.wait_group %0;" :: "n"(n) : "memory")

#define LDSM4(r0, r1, r2, r3, addr) \
    asm volatile("ldmatrix.sync.aligned.m8n8.x4.shared.b16 {%0,%1,%2,%3}, [%4];" \
                 : "=r"(r0), "=r"(r1), "=r"(r2), "=r"(r3) : "r"(addr))
#define LDSM4T(r0, r1, r2, r3, addr) \
    asm volatile("ldmatrix.sync.aligned.m8n8.x4.trans.shared.b16 {%0,%1,%2,%3}, [%4];" \
                 : "=r"(r0), "=r"(r1), "=r"(r2), "=r"(r3) : "r"(addr))

#define MMA_BF16(d, a, b0, b1) \
    asm volatile("mma.sync.aligned.m16n8k16.row.col.f32.bf16.bf16.f32 " \
                 "{%0,%1,%2,%3}, {%4,%5,%6,%7}, {%8,%9}, {%0,%1,%2,%3};" \
                 : "+f"((d)[0]), "+f"((d)[1]), "+f"((d)[2]), "+f"((d)[3]) \
                 : "r"((a)[0]), "r"((a)[1]), "r"((a)[2]), "r"((a)[3]), \
                   "r"(b0), "r"(b1))

__device__ __forceinline__ void split2(float a, float b, uint32_t& hi, uint32_t& lo) {
    __nv_bfloat162 h = __floats2bfloat162_rn(a, b);
    float ra = a - __bfloat162float(h.x);
    float rb = b - __bfloat162float(h.y);
    __nv_bfloat162 l = __floats2bfloat162_rn(ra, rb);
    hi = *(uint32_t*)&h;
    lo = *(uint32_t*)&l;
}

// ---------------------------------------------------------------------------
// fp32 -> bf16 hi/lo split
// ---------------------------------------------------------------------------
__global__ __launch_bounds__(256) void split_kernel(
    const float* __restrict__ src, __nv_bfloat16* __restrict__ hi,
    __nv_bfloat16* __restrict__ lo, int n4)
{
    int i = blockIdx.x * blockDim.x + threadIdx.x;
    if (i >= n4) return;
    float4 v = ((const float4*)src)[i];
    uint32_t h0, l0, h1, l1;
    split2(v.x, v.y, h0, l0);
    split2(v.z, v.w, h1, l1);
    ((uint32_t*)hi)[2 * i] = h0;  ((uint32_t*)hi)[2 * i + 1] = h1;
    ((uint32_t*)lo)[2 * i] = l0;  ((uint32_t*)lo)[2 * i + 1] = l1;
}

// ---------------------------------------------------------------------------
// bf16 mma.sync GEMM, split-as-K-extension (96 chunks of BK=32).
// 4-stage cp.async ring, ONE __syncthreads per chunk.
// chunk c is in async-group c+1 (3 prologue commits + 1 commit/iter);
// wait_group(2) at iter c => group c+1 complete.
// ---------------------------------------------------------------------------
#define GK 1024
#define GN 1024
#define LDT 40
#define GT_B   (128 * LDT * 2)        // 10240 B per matrix tile
#define GST_B  (2 * GT_B)             // stage: A + B = 20480 B
#define GEMM_SMEM (4 * GST_B)         // 81920 B

template <bool SPLIT_OUT>
__global__ __launch_bounds__(256, 2) void gemm_mma(
    const __nv_bfloat16* __restrict__ Ahi, const __nv_bfloat16* __restrict__ Alo,
    const __nv_bfloat16* __restrict__ Bhi, const __nv_bfloat16* __restrict__ Blo,
    const float* __restrict__ bias, float* __restrict__ C,
    __nv_bfloat16* __restrict__ Chi, __nv_bfloat16* __restrict__ Clo)
{
    extern __shared__ __align__(128) char smg[];
    const uint32_t smb = smem_u32(smg);

    const int tid = threadIdx.x;
    const int wid = tid >> 5;
    const int lane = tid & 31;
    const int bn = blockIdx.x * 128;
    const int bm = blockIdx.y * 128;
    const int wr = (wid & 1) * 64;
    const int wc = (wid >> 1) * 32;

    float acc[4][4][4];
#pragma unroll
    for (int mt = 0; mt < 4; mt++)
#pragma unroll
        for (int j = 0; j < 4; j++)
#pragma unroll
            for (int r = 0; r < 4; r++) acc[mt][j][r] = 0.0f;

    auto load_chunk = [&](int c, int stg) {
        const __nv_bfloat16* Ap = (c >= 64) ? Alo : Ahi;
        const __nv_bfloat16* Bp = (c >= 32 && c < 64) ? Blo : Bhi;
        const int k0 = (c & 31) * 32;
        const uint32_t sa = smb + stg * GST_B;
#pragma unroll
        for (int it = 0; it < 2; it++) {
            int idx = tid + it * 256;
            int r = idx >> 2, u = idx & 3;
            CP16(sa + (uint32_t)(r * LDT) * 2 + u * 16,
                 Ap + (size_t)(bm + r) * GK + k0 + u * 8);
        }
#pragma unroll
        for (int it = 0; it < 2; it++) {
            int idx = tid + it * 256;
            int r = idx >> 2, u = idx & 3;
            CP16(sa + GT_B + (uint32_t)(r * LDT) * 2 + u * 16,
                 Bp + (size_t)(bn + r) * GK + k0 + u * 8);
        }
    };

    auto compute = [&](int stg) {
        const uint32_t sa = smb + stg * GST_B;
#pragma unroll
        for (int ks = 0; ks < 2; ks++) {
            const int colb = ks * 32 + (lane >> 4) * 16;
            uint32_t a[4][4], b[2][4];
#pragma unroll
            for (int mt = 0; mt < 4; mt++) {
                uint32_t ad = sa + (uint32_t)((wr + mt * 16 + (lane & 15)) * LDT) * 2 + colb;
                LDSM4(a[mt][0], a[mt][1], a[mt][2], a[mt][3], ad);
            }
#pragma unroll
            for (int ng = 0; ng < 2; ng++) {
                uint32_t bd = sa + GT_B + (uint32_t)((wc + ng * 16 + (lane & 15)) * LDT) * 2 + colb;
                LDSM4(b[ng][0], b[ng][1], b[ng][2], b[ng][3], bd);
            }
#pragma unroll
            for (int mt = 0; mt < 4; mt++)
#pragma unroll
                for (int j = 0; j < 4; j++)
                    MMA_BF16(acc[mt][j], a[mt], b[j >> 1][j & 1], b[j >> 1][(j & 1) + 2]);
        }
    };

    load_chunk(0, 0); CP_COMMIT();
    load_chunk(1, 1); CP_COMMIT();
    load_chunk(2, 2); CP_COMMIT();

    for (int c = 0; c < 96; c++) {
        CP_WAIT(2);
        __syncthreads();
        if (c + 3 < 96) load_chunk(c + 3, (c + 3) & 3);
        CP_COMMIT();
        compute(c & 3);
    }

    const int rq = lane >> 2;
    const int cq = (lane & 3) * 2;
#pragma unroll
    for (int mt = 0; mt < 4; mt++) {
#pragma unroll
        for (int j = 0; j < 4; j++) {
            const int col = bn + wc + j * 8 + cq;
            const float b0 = bias[col], b1 = bias[col + 1];
            const int row0 = bm + wr + mt * 16 + rq;
            float v0 = acc[mt][j][0] + b0, v1 = acc[mt][j][1] + b1;
            float v2 = acc[mt][j][2] + b0, v3 = acc[mt][j][3] + b1;
            if (SPLIT_OUT) {
                uint32_t h01, l01;
                split2(v0, v1, h01, l01);
                *(uint32_t*)(Chi + (size_t)row0 * GN + col) = h01;
                *(uint32_t*)(Clo + (size_t)row0 * GN + col) = l01;
                split2(v2, v3, h01, l01);
                *(uint32_t*)(Chi + (size_t)(row0 + 8) * GN + col) = h01;
                *(uint32_t*)(Clo + (size_t)(row0 + 8) * GN + col) = l01;
            } else {
                *(float2*)(C + (size_t)row0 * GN + col) = make_float2(v0, v1);
                *(float2*)(C + (size_t)(row0 + 8) * GN + col) = make_float2(v2, v3);
            }
        }
    }
}

// ---------------------------------------------------------------------------
// Flash attention, bf16 mma.sync, causal.
// 3-stage KV ring, ONE __syncthreads per KV tile.
// kv_j is in async-group j+1 (2 prologue commits + 1 commit/iter);
// wait_group(1) at iter kt => group kt+1 complete.
// ---------------------------------------------------------------------------
#define ALD 72
#define AQ_B  (128 * ALD * 2)          // 18432 B per Q matrix
#define AM_B  (64 * ALD * 2)           // 9216 B per K/V matrix
#define AST_B (4 * AM_B)               // stage: Kh,Kl,Vh,Vl = 36864 B
#define ATTN_SMEM (2 * AQ_B + 3 * AST_B)   // 147456 B

__global__ __launch_bounds__(256) void attn_mma(
    const __nv_bfloat16* __restrict__ Qhi, const __nv_bfloat16* __restrict__ Qlo,
    const __nv_bfloat16* __restrict__ Khi, const __nv_bfloat16* __restrict__ Klo,
    const __nv_bfloat16* __restrict__ Vhi, const __nv_bfloat16* __restrict__ Vlo,
    __nv_bfloat16* __restrict__ Ohi, __nv_bfloat16* __restrict__ Olo)
{
    extern __shared__ __align__(128) char smc[];
    const uint32_t smb = smem_u32(smc);
    const int tid = threadIdx.x;
    const int wid = tid >> 5;
    const int lane = tid & 31;
    const int qt = (int)gridDim.x - 1 - (int)blockIdx.x;
    const int h = blockIdx.y, b = blockIdx.z;
    const int q0 = qt * 128;
    const size_t rc0 = (size_t)b * SEQ * D_MODEL + h * HDIM;

    const int wr = wid * 16;
    const uint32_t lrow = lane & 15;
    const uint32_t lc16 = (lane >> 4) * 16;

    auto load_q = [&] {
#pragma unroll
        for (int it = 0; it < 8; it++) {
            int t = tid + it * 256;
            const __nv_bfloat16* src = (t < 1024) ? Qhi : Qlo;
            uint32_t moff = (t < 1024) ? 0u : (uint32_t)AQ_B;
            int idx = t & 1023, r = idx >> 3, u = idx & 7;
            CP16(smb + moff + (uint32_t)(r * ALD + u * 8) * 2,
                 src + rc0 + (size_t)(q0 + r) * D_MODEL + u * 8);
        }
    };
    auto load_kv = [&](int kt, int stg) {
        const uint32_t sb = smb + 2 * AQ_B + stg * AST_B;
#pragma unroll
        for (int it = 0; it < 8; it++) {
            int t = tid + it * 256;
            int mtx = t >> 9;
            int idx = t & 511, r = idx >> 3, u = idx & 7;
            const __nv_bfloat16* src = (mtx == 0) ? Khi : (mtx == 1) ? Klo
                                      : (mtx == 2) ? Vhi : Vlo;
            CP16(sb + mtx * AM_B + (uint32_t)(r * ALD + u * 8) * 2,
                 src + rc0 + (size_t)(kt * 64 + r) * D_MODEL + u * 8);
        }
    };

    float o[8][4];
#pragma unroll
    for (int nt = 0; nt < 8; nt++)
#pragma unroll
        for (int c = 0; c < 4; c++) o[nt][c] = 0.0f;
    float m0 = -1e30f, m1 = -1e30f, l0 = 0.0f, l1 = 0.0f;
    uint32_t qh[4][4], ql[4][4];

    const int ktEnd = 2 * qt + 2;
    load_q();
    load_kv(0, 0);
    CP_COMMIT();                       // group 1: Q + kv0
    if (1 < ktEnd) load_kv(1, 1);
    CP_COMMIT();                       // group 2: kv1

    for (int kt = 0; kt < ktEnd; kt++) {
        CP_WAIT(1);
        __syncthreads();
        if (kt + 2 < ktEnd) load_kv(kt + 2, (kt + 2) % 3);
        CP_COMMIT();

        if (kt == 0) {
#pragma unroll
            for (int ks = 0; ks < 4; ks++) {
                uint32_t a1 = smb + (uint32_t)((wr + lrow) * ALD) * 2 + ks * 32 + lc16;
                LDSM4(qh[ks][0], qh[ks][1], qh[ks][2], qh[ks][3], a1);
                LDSM4(ql[ks][0], ql[ks][1], ql[ks][2], ql[ks][3], a1 + AQ_B);
            }
        }

        const uint32_t sb = smb + 2 * AQ_B + (kt % 3) * AST_B;

        // ---- S = Q K^T (3 split terms) ----
        float s[8][4];
#pragma unroll
        for (int nt = 0; nt < 8; nt++)
#pragma unroll
            for (int c = 0; c < 4; c++) s[nt][c] = 0.0f;

#pragma unroll
        for (int ks = 0; ks < 4; ks++) {
            uint32_t kf[4][4];
#pragma unroll
            for (int ng = 0; ng < 4; ng++) {
                uint32_t a1 = sb + (uint32_t)((ng * 16 + lrow) * ALD) * 2 + ks * 32 + lc16;
                LDSM4(kf[ng][0], kf[ng][1], kf[ng][2], kf[ng][3], a1);
            }
#pragma unroll
            for (int nt = 0; nt < 8; nt++) {
                MMA_BF16(s[nt], qh[ks], kf[nt >> 1][nt & 1], kf[nt >> 1][(nt & 1) + 2]);
                MMA_BF16(s[nt], ql[ks], kf[nt >> 1][nt & 1], kf[nt >> 1][(nt & 1) + 2]);
            }
#pragma unroll
            for (int ng = 0; ng < 4; ng++) {
                uint32_t a1 = sb + AM_B + (uint32_t)((ng * 16 + lrow) * ALD) * 2 + ks * 32 + lc16;
                LDSM4(kf[ng][0], kf[ng][1], kf[ng][2], kf[ng][3], a1);
            }
#pragma unroll
            for (int nt = 0; nt < 8; nt++)
                MMA_BF16(s[nt], qh[ks], kf[nt >> 1][nt & 1], kf[nt >> 1][(nt & 1) + 2]);
        }

#pragma unroll
        for (int nt = 0; nt < 8; nt++)
#pragma unroll
            for (int c = 0; c < 4; c++) s[nt][c] *= 0.125f;

        // ---- causal mask (diagonal tiles only) ----
        if (kt * 64 + 63 > q0 + wr) {
            const int r0 = q0 + wr + (lane >> 2);
#pragma unroll
            for (int nt = 0; nt < 8; nt++) {
                const int c0 = kt * 64 + nt * 8 + 2 * (lane & 3);
                if (c0 > r0)         s[nt][0] = -1e30f;
                if (c0 + 1 > r0)     s[nt][1] = -1e30f;
                if (c0 > r0 + 8)     s[nt][2] = -1e30f;
                if (c0 + 1 > r0 + 8) s[nt][3] = -1e30f;
            }
        }

        // ---- online softmax (fp32, quad shuffles) ----
        float mx0 = -1e30f, mx1 = -1e30f;
#pragma unroll
        for (int nt = 0; nt < 8; nt++) {
            mx0 = fmaxf(mx0, fmaxf(s[nt][0], s[nt][1]));
            mx1 = fmaxf(mx1, fmaxf(s[nt][2], s[nt][3]));
        }
        mx0 = fmaxf(mx0, __shfl_xor_sync(0xffffffffu, mx0, 1));
        mx0 = fmaxf(mx0, __shfl_xor_sync(0xffffffffu, mx0, 2));
        mx1 = fmaxf(mx1, __shfl_xor_sync(0xffffffffu, mx1, 1));
        mx1 = fmaxf(mx1, __shfl_xor_sync(0xffffffffu, mx1, 2));
        const float n0 = fmaxf(m0, mx0), n1 = fmaxf(m1, mx1);
        const float cr0 = __expf(m0 - n0), cr1 = __expf(m1 - n1);
        m0 = n0; m1 = n1;
        float sum0 = 0.0f, sum1 = 0.0f;
#pragma unroll
        for (int nt = 0; nt < 8; nt++) {
            s[nt][0] = __expf(s[nt][0] - n0); sum0 += s[nt][0];
            s[nt][1] = __expf(s[nt][1] - n0); sum0 += s[nt][1];
            s[nt][2] = __expf(s[nt][2] - n1); sum1 += s[nt][2];
            s[nt][3] = __expf(s[nt][3] - n1); sum1 += s[nt][3];
        }
        sum0 += __shfl_xor_sync(0xffffffffu, sum0, 1);
        sum0 += __shfl_xor_sync(0xffffffffu, sum0, 2);
        sum1 += __shfl_xor_sync(0xffffffffu, sum1, 1);
        sum1 += __shfl_xor_sync(0xffffffffu, sum1, 2);
        l0 = l0 * cr0 + sum0;
        l1 = l1 * cr1 + sum1;
#pragma unroll
        for (int nt = 0; nt < 8; nt++) {
            o[nt][0] *= cr0; o[nt][1] *= cr0;
            o[nt][2] *= cr1; o[nt][3] *= cr1;
        }

        // ---- P fragments (bf16 hi + residual) ----
        uint32_t ph[4][4], pl[4][4];
#pragma unroll
        for (int ks = 0; ks < 4; ks++) {
            split2(s[2 * ks][0], s[2 * ks][1], ph[ks][0], pl[ks][0]);
            split2(s[2 * ks][2], s[2 * ks][3], ph[ks][1], pl[ks][1]);
            split2(s[2 * ks + 1][0], s[2 * ks + 1][1], ph[ks][2], pl[ks][2]);
            split2(s[2 * ks + 1][2], s[2 * ks + 1][3], ph[ks][3], pl[ks][3]);
        }

        // ---- O += P V (3 split terms) ----
#pragma unroll
        for (int ks = 0; ks < 4; ks++) {
            uint32_t vh[4][4], vl[4][4];
#pragma unroll
            for (int ng = 0; ng < 4; ng++) {
                uint32_t a1 = sb + 2 * AM_B + (uint32_t)((ks * 16 + lrow) * ALD) * 2 + ng * 32 + lc16;
                LDSM4T(vh[ng][0], vh[ng][1], vh[ng][2], vh[ng][3], a1);
                LDSM4T(vl[ng][0], vl[ng][1], vl[ng][2], vl[ng][3], a1 + AM_B);
            }
#pragma unroll
            for (int nt = 0; nt < 8; nt++) {
                const uint32_t b0 = vh[nt >> 1][(nt & 1) * 2];
                const uint32_t b1 = vh[nt >> 1][(nt & 1) * 2 + 1];
                MMA_BF16(o[nt], ph[ks], b0, b1);
                MMA_BF16(o[nt], pl[ks], b0, b1);
                MMA_BF16(o[nt], ph[ks], vl[nt >> 1][(nt & 1) * 2], vl[nt >> 1][(nt & 1) * 2 + 1]);
            }
        }
    }

    // ---- epilogue ----
    const float i0 = 1.0f / l0, i1 = 1.0f / l1;
    const size_t r0 = (size_t)(b * SEQ + q0 + wr + (lane >> 2));
    const int colb = h * HDIM + 2 * (lane & 3);
#pragma unroll
    for (int nt = 0; nt < 8; nt++) {
        const int col = colb + nt * 8;
        uint32_t h01, l01;
        split2(o[nt][0] * i0, o[nt][1] * i0, h01, l01);
        *(uint32_t*)(Ohi + r0 * D_MODEL + col) = h01;
        *(uint32_t*)(Olo + r0 * D_MODEL + col) = l01;
        split2(o[nt][2] * i1, o[nt][3] * i1, h01, l01);
        *(uint32_t*)(Ohi + (r0 + 8) * D_MODEL + col) = h01;
        *(uint32_t*)(Olo + (r0 + 8) * D_MODEL + col) = l01;
    }
}

// ---------------------------------------------------------------------------
// Launch
// ---------------------------------------------------------------------------
extern "C" void kernel_launch(void* const* d_in, const int* in_sizes, int n_in,
                              void* d_out, int out_size)
{
    (void)in_sizes; (void)n_in; (void)out_size;
    const float* x  = (const float*)d_in[0];
    const float* Wq = (const float*)d_in[1];
    const float* bq = (const float*)d_in[2];
    const float* Wk = (const float*)d_in[3];
    const float* bk = (const float*)d_in[4];
    const float* Wv = (const float*)d_in[5];
    const float* bv = (const float*)d_in[6];
    const float* Wo = (const float*)d_in[7];
    const float* bo = (const float*)d_in[8];
    float* out = (float*)d_out;

    __nv_bfloat16 *xhi, *xlo, *whi, *wlo;
    __nv_bfloat16 *qhi, *qlo, *khi, *klo, *vhi, *vlo, *ohi, *olo;
    cudaGetSymbolAddress((void**)&xhi, g_xhi);
    cudaGetSymbolAddress((void**)&xlo, g_xlo);
    cudaGetSymbolAddress((void**)&whi, g_whi);
    cudaGetSymbolAddress((void**)&wlo, g_wlo);
    cudaGetSymbolAddress((void**)&qhi, g_qhi);
    cudaGetSymbolAddress((void**)&qlo, g_qlo);
    cudaGetSymbolAddress((void**)&khi, g_khi);
    cudaGetSymbolAddress((void**)&klo, g_klo);
    cudaGetSymbolAddress((void**)&vhi, g_vhi);
    cudaGetSymbolAddress((void**)&vlo, g_vlo);
    cudaGetSymbolAddress((void**)&ohi, g_ohi);
    cudaGetSymbolAddress((void**)&olo, g_olo);

    cudaFuncSetAttribute(attn_mma,
                         cudaFuncAttributeMaxDynamicSharedMemorySize, ATTN_SMEM);
    cudaFuncSetAttribute(gemm_mma<true>,
                         cudaFuncAttributeMaxDynamicSharedMemorySize, GEMM_SMEM);
    cudaFuncSetAttribute(gemm_mma<false>,
                         cudaFuncAttributeMaxDynamicSharedMemorySize, GEMM_SMEM);

    const int WN = D_MODEL * D_MODEL;
    const int n4x = MTOT * D_MODEL / 4;
    const int n4w = WN / 4;

    split_kernel<<<(n4x + 255) / 256, 256>>>(x, xhi, xlo, n4x);
    split_kernel<<<(n4w + 255) / 256, 256>>>(Wq, whi + 0 * WN, wlo + 0 * WN, n4w);
    split_kernel<<<(n4w + 255) / 256, 256>>>(Wk, whi + 1 * WN, wlo + 1 * WN, n4w);
    split_kernel<<<(n4w + 255) / 256, 256>>>(Wv, whi + 2 * WN, wlo + 2 * WN, n4w);
    split_kernel<<<(n4w + 255) / 256, 256>>>(Wo, whi + 3 * WN, wlo + 3 * WN, n4w);

    dim3 gGemm(GN / 128, MTOT / 128);          // (8, 32)
    gemm_mma<true><<<gGemm, 256, GEMM_SMEM>>>(xhi, xlo, whi + 0 * WN, wlo + 0 * WN, bq,
                                              nullptr, qhi, qlo);
    gemm_mma<true><<<gGemm, 256, GEMM_SMEM>>>(xhi, xlo, whi + 1 * WN, wlo + 1 * WN, bk,
                                              nullptr, khi, klo);
    gemm_mma<true><<<gGemm, 256, GEMM_SMEM>>>(xhi, xlo, whi + 2 * WN, wlo + 2 * WN, bv,
                                              nullptr, vhi, vlo);

    dim3 gAttn(SEQ / 128, NHEAD, BATCH);       // (16, 16, 2)
    attn_mma<<<gAttn, 256, ATTN_SMEM>>>(qhi, qlo, khi, klo, vhi, vlo, ohi, olo);

    gemm_mma<false><<<gGemm, 256, GEMM_SMEM>>>(ohi, olo, whi + 3 * WN, wlo + 3 * WN, bo,
                                               out, nullptr, nullptr);
}

// round 6
// speedup vs baseline: 3.0741x; 1.4280x over previous
#include <cuda_runtime.h>
#include <cuda_fp16.h>
#include <cstdint>
#include <cstddef>

#define D_MODEL 1024
#define SEQ     2048
#define BATCH   2
#define NHEAD   16
#define HDIM    64
#define MTOT    (BATCH * SEQ)          // 4096 rows

// ---------------------------------------------------------------------------
// Scratch (no cudaMalloc allowed) — fp16
// ---------------------------------------------------------------------------
__device__ __half g_xh[MTOT * D_MODEL];
__device__ __half g_xl[MTOT * D_MODEL];
__device__ __half g_wh[4 * D_MODEL * D_MODEL];
__device__ __half g_qh[MTOT * D_MODEL];
__device__ __half g_ql[MTOT * D_MODEL];
__device__ __half g_kh[MTOT * D_MODEL];
__device__ __half g_vh[MTOT * D_MODEL];
__device__ __half g_oh[MTOT * D_MODEL];
__device__ __half g_ol[MTOT * D_MODEL];

// ---------------------------------------------------------------------------
// PTX helpers (sm_100-safe)
// ---------------------------------------------------------------------------
__device__ __forceinline__ uint32_t smem_u32(const void* p) {
    uint32_t a;
    asm("{ .reg .u64 t; cvta.to.shared.u64 t, %1; cvt.u32.u64 %0, t; }" : "=r"(a) : "l"(p));
    return a;
}
#define CP16(dst, src) \
    asm volatile("cp.async.cg.shared.global [%0], [%1], 16;" :: "r"(dst), "l"(src))
#define CP_COMMIT() asm volatile("cp.async.commit_group;" ::: "memory")
#define CP_WAIT(n)  asm volatile("cp.async.wait_group %0;" :: "n"(n) : "memory")

#define LDSM4(r0, r1, r2, r3, addr) \
    asm volatile("ldmatrix.sync.aligned.m8n8.x4.shared.b16 {%0,%1,%2,%3}, [%4];" \
                 : "=r"(r0), "=r"(r1), "=r"(r2), "=r"(r3) : "r"(addr))
#define LDSM4T(r0, r1, r2, r3, addr) \
    asm volatile("ldmatrix.sync.aligned.m8n8.x4.trans.shared.b16 {%0,%1,%2,%3}, [%4];" \
                 : "=r"(r0), "=r"(r1), "=r"(r2), "=r"(r3) : "r"(addr))

#define MMA_F16(d, a, b0, b1) \
    asm volatile("mma.sync.aligned.m16n8k16.row.col.f32.f16.f16.f32 " \
                 "{%0,%1,%2,%3}, {%4,%5,%6,%7}, {%8,%9}, {%0,%1,%2,%3};" \
                 : "+f"((d)[0]), "+f"((d)[1]), "+f"((d)[2]), "+f"((d)[3]) \
                 : "r"((a)[0]), "r"((a)[1]), "r"((a)[2]), "r"((a)[3]), \
                   "r"(b0), "r"(b1))

// exact fp16 hi + residual split of two fp32 values
__device__ __forceinline__ void split2h(float a, float b, uint32_t& hi, uint32_t& lo) {
    __half2 h = __floats2half2_rn(a, b);
    float ra = a - __half2float(__low2half(h));
    float rb = b - __half2float(__high2half(h));
    __half2 l = __floats2half2_rn(ra, rb);
    hi = *(uint32_t*)&h;
    lo = *(uint32_t*)&l;
}

// ---------------------------------------------------------------------------
// fp32 -> fp16 hi/lo split (activations)
// ---------------------------------------------------------------------------
__global__ __launch_bounds__(256) void split_kernel(
    const float* __restrict__ src, __half* __restrict__ hi,
    __half* __restrict__ lo, int n4)
{
    int i = blockIdx.x * blockDim.x + threadIdx.x;
    if (i >= n4) return;
    float4 v = ((const float4*)src)[i];
    uint32_t h0, l0, h1, l1;
    split2h(v.x, v.y, h0, l0);
    split2h(v.z, v.w, h1, l1);
    ((uint32_t*)hi)[2 * i] = h0;  ((uint32_t*)hi)[2 * i + 1] = h1;
    ((uint32_t*)lo)[2 * i] = l0;  ((uint32_t*)lo)[2 * i + 1] = l1;
}

// fp32 -> fp16 convert (weights, hi only)
__global__ __launch_bounds__(256) void cvt_kernel(
    const float* __restrict__ src, __half* __restrict__ dst, int n4)
{
    int i = blockIdx.x * blockDim.x + threadIdx.x;
    if (i >= n4) return;
    float4 v = ((const float4*)src)[i];
    __half2 a = __floats2half2_rn(v.x, v.y);
    __half2 b = __floats2half2_rn(v.z, v.w);
    ((__half2*)dst)[2 * i] = a;
    ((__half2*)dst)[2 * i + 1] = b;
}

// ---------------------------------------------------------------------------
// fp16 mma.sync GEMM: C[M,1024] = (Ahi+Alo)[M,1024] @ W[1024,1024]^T + bias
// 64 chunks of BK=32: c<32 -> Ahi*W, c>=32 -> Alo*W.
// 4-stage cp.async ring, one __syncthreads per chunk.
// OUT_MODE: 0 = fp32 + bias, 1 = fp16 hi+lo, 2 = fp16 hi only
// ---------------------------------------------------------------------------
#define GK 1024
#define GN 1024
#define LDT 40
#define GT_B   (128 * LDT * 2)        // 10240 B per matrix tile
#define GST_B  (2 * GT_B)             // stage: A + B = 20480 B
#define GEMM_SMEM (4 * GST_B)         // 81920 B
#define NCH 64

template <int OUT_MODE>
__global__ __launch_bounds__(256, 2) void gemm_mma(
    const __half* __restrict__ Ahi, const __half* __restrict__ Alo,
    const __half* __restrict__ W,
    const float* __restrict__ bias, float* __restrict__ C,
    __half* __restrict__ Chi, __half* __restrict__ Clo)
{
    extern __shared__ __align__(128) char smg[];
    const uint32_t smb = smem_u32(smg);

    const int tid = threadIdx.x;
    const int wid = tid >> 5;
    const int lane = tid & 31;
    const int bn = blockIdx.x * 128;
    const int bm = blockIdx.y * 128;
    const int wr = (wid & 1) * 64;
    const int wc = (wid >> 1) * 32;

    float acc[4][4][4];
#pragma unroll
    for (int mt = 0; mt < 4; mt++)
#pragma unroll
        for (int j = 0; j < 4; j++)
#pragma unroll
            for (int r = 0; r < 4; r++) acc[mt][j][r] = 0.0f;

    auto load_chunk = [&](int c, int stg) {
        const __half* Ap = (c >= 32) ? Alo : Ahi;
        const int k0 = (c & 31) * 32;
        const uint32_t sa = smb + stg * GST_B;
#pragma unroll
        for (int it = 0; it < 2; it++) {
            int idx = tid + it * 256;
            int r = idx >> 2, u = idx & 3;
            CP16(sa + (uint32_t)(r * LDT) * 2 + u * 16,
                 Ap + (size_t)(bm + r) * GK + k0 + u * 8);
        }
#pragma unroll
        for (int it = 0; it < 2; it++) {
            int idx = tid + it * 256;
            int r = idx >> 2, u = idx & 3;
            CP16(sa + GT_B + (uint32_t)(r * LDT) * 2 + u * 16,
                 W + (size_t)(bn + r) * GK + k0 + u * 8);
        }
    };

    auto compute = [&](int stg) {
        const uint32_t sa = smb + stg * GST_B;
#pragma unroll
        for (int ks = 0; ks < 2; ks++) {
            const int colb = ks * 32 + (lane >> 4) * 16;
            uint32_t a[4][4], b[2][4];
#pragma unroll
            for (int mt = 0; mt < 4; mt++) {
                uint32_t ad = sa + (uint32_t)((wr + mt * 16 + (lane & 15)) * LDT) * 2 + colb;
                LDSM4(a[mt][0], a[mt][1], a[mt][2], a[mt][3], ad);
            }
#pragma unroll
            for (int ng = 0; ng < 2; ng++) {
                uint32_t bd = sa + GT_B + (uint32_t)((wc + ng * 16 + (lane & 15)) * LDT) * 2 + colb;
                LDSM4(b[ng][0], b[ng][1], b[ng][2], b[ng][3], bd);
            }
#pragma unroll
            for (int mt = 0; mt < 4; mt++)
#pragma unroll
                for (int j = 0; j < 4; j++)
                    MMA_F16(acc[mt][j], a[mt], b[j >> 1][j & 1], b[j >> 1][(j & 1) + 2]);
        }
    };

    load_chunk(0, 0); CP_COMMIT();
    load_chunk(1, 1); CP_COMMIT();
    load_chunk(2, 2); CP_COMMIT();

    for (int c = 0; c < NCH; c++) {
        CP_WAIT(2);
        __syncthreads();
        if (c + 3 < NCH) load_chunk(c + 3, (c + 3) & 3);
        CP_COMMIT();
        compute(c & 3);
    }

    const int rq = lane >> 2;
    const int cq = (lane & 3) * 2;
#pragma unroll
    for (int mt = 0; mt < 4; mt++) {
#pragma unroll
        for (int j = 0; j < 4; j++) {
            const int col = bn + wc + j * 8 + cq;
            const float b0 = bias[col], b1 = bias[col + 1];
            const int row0 = bm + wr + mt * 16 + rq;
            float v0 = acc[mt][j][0] + b0, v1 = acc[mt][j][1] + b1;
            float v2 = acc[mt][j][2] + b0, v3 = acc[mt][j][3] + b1;
            if (OUT_MODE == 0) {
                *(float2*)(C + (size_t)row0 * GN + col) = make_float2(v0, v1);
                *(float2*)(C + (size_t)(row0 + 8) * GN + col) = make_float2(v2, v3);
            } else if (OUT_MODE == 1) {
                uint32_t h01, l01;
                split2h(v0, v1, h01, l01);
                *(uint32_t*)(Chi + (size_t)row0 * GN + col) = h01;
                *(uint32_t*)(Clo + (size_t)row0 * GN + col) = l01;
                split2h(v2, v3, h01, l01);
                *(uint32_t*)(Chi + (size_t)(row0 + 8) * GN + col) = h01;
                *(uint32_t*)(Clo + (size_t)(row0 + 8) * GN + col) = l01;
            } else {
                __half2 h0 = __floats2half2_rn(v0, v1);
                __half2 h1 = __floats2half2_rn(v2, v3);
                *(__half2*)(Chi + (size_t)row0 * GN + col) = h0;
                *(__half2*)(Chi + (size_t)(row0 + 8) * GN + col) = h1;
            }
        }
    }
}

// ---------------------------------------------------------------------------
// Flash attention, fp16 mma.sync, causal.
// Q exact-split (qh+ql); K, V single fp16.
// S = qh*K + ql*K;  O += ph*V + pl*V  (P exact-split).
// 4-stage KV ring (Kh+Vh per stage), one __syncthreads per KV tile.
// ---------------------------------------------------------------------------
#define ALD 72
#define AQ_B  (128 * ALD * 2)          // 18432 B per Q matrix
#define AM_B  (64 * ALD * 2)           // 9216 B per K/V matrix
#define AST_B (2 * AM_B)               // stage: Kh,Vh = 18432 B
#define ATTN_SMEM (2 * AQ_B + 4 * AST_B)   // 110592 B

__global__ __launch_bounds__(256) void attn_mma(
    const __half* __restrict__ Qhi, const __half* __restrict__ Qlo,
    const __half* __restrict__ Kh, const __half* __restrict__ Vh,
    __half* __restrict__ Ohi, __half* __restrict__ Olo)
{
    extern __shared__ __align__(128) char smc[];
    const uint32_t smb = smem_u32(smc);
    const int tid = threadIdx.x;
    const int wid = tid >> 5;
    const int lane = tid & 31;
    const int qt = (int)gridDim.x - 1 - (int)blockIdx.x;
    const int h = blockIdx.y, b = blockIdx.z;
    const int q0 = qt * 128;
    const size_t rc0 = (size_t)b * SEQ * D_MODEL + h * HDIM;

    const int wr = wid * 16;
    const uint32_t lrow = lane & 15;
    const uint32_t lc16 = (lane >> 4) * 16;

    auto load_q = [&] {
#pragma unroll
        for (int it = 0; it < 8; it++) {
            int t = tid + it * 256;
            const __half* src = (t < 1024) ? Qhi : Qlo;
            uint32_t moff = (t < 1024) ? 0u : (uint32_t)AQ_B;
            int idx = t & 1023, r = idx >> 3, u = idx & 7;
            CP16(smb + moff + (uint32_t)(r * ALD + u * 8) * 2,
                 src + rc0 + (size_t)(q0 + r) * D_MODEL + u * 8);
        }
    };
    auto load_kv = [&](int kt, int stg) {
        const uint32_t sb = smb + 2 * AQ_B + stg * AST_B;
#pragma unroll
        for (int it = 0; it < 4; it++) {
            int t = tid + it * 256;                 // 0..1023
            int mtx = t >> 9;                       // 0:Kh 1:Vh
            int idx = t & 511, r = idx >> 3, u = idx & 7;
            const __half* src = (mtx == 0) ? Kh : Vh;
            CP16(sb + mtx * AM_B + (uint32_t)(r * ALD + u * 8) * 2,
                 src + rc0 + (size_t)(kt * 64 + r) * D_MODEL + u * 8);
        }
    };

    float o[8][4];
#pragma unroll
    for (int nt = 0; nt < 8; nt++)
#pragma unroll
        for (int c = 0; c < 4; c++) o[nt][c] = 0.0f;
    float m0 = -1e30f, m1 = -1e30f, l0 = 0.0f, l1 = 0.0f;
    uint32_t qh[4][4], ql[4][4];

    const int ktEnd = 2 * qt + 2;
    load_q();
    load_kv(0, 0);
    CP_COMMIT();                       // group 1: Q + kv0
    if (1 < ktEnd) load_kv(1, 1);
    CP_COMMIT();                       // group 2: kv1
    if (2 < ktEnd) load_kv(2, 2);
    CP_COMMIT();                       // group 3: kv2

    for (int kt = 0; kt < ktEnd; kt++) {
        CP_WAIT(2);
        __syncthreads();
        if (kt + 3 < ktEnd) load_kv(kt + 3, (kt + 3) & 3);
        CP_COMMIT();

        if (kt == 0) {
#pragma unroll
            for (int ks = 0; ks < 4; ks++) {
                uint32_t a1 = smb + (uint32_t)((wr + lrow) * ALD) * 2 + ks * 32 + lc16;
                LDSM4(qh[ks][0], qh[ks][1], qh[ks][2], qh[ks][3], a1);
                LDSM4(ql[ks][0], ql[ks][1], ql[ks][2], ql[ks][3], a1 + AQ_B);
            }
        }

        const uint32_t sb = smb + 2 * AQ_B + (kt & 3) * AST_B;

        // ---- S = (qh+ql) K^T ----
        float s[8][4];
#pragma unroll
        for (int nt = 0; nt < 8; nt++)
#pragma unroll
            for (int c = 0; c < 4; c++) s[nt][c] = 0.0f;

#pragma unroll
        for (int ks = 0; ks < 4; ks++) {
            uint32_t kf[4][4];
#pragma unroll
            for (int ng = 0; ng < 4; ng++) {
                uint32_t a1 = sb + (uint32_t)((ng * 16 + lrow) * ALD) * 2 + ks * 32 + lc16;
                LDSM4(kf[ng][0], kf[ng][1], kf[ng][2], kf[ng][3], a1);
            }
#pragma unroll
            for (int nt = 0; nt < 8; nt++) {
                MMA_F16(s[nt], qh[ks], kf[nt >> 1][nt & 1], kf[nt >> 1][(nt & 1) + 2]);
                MMA_F16(s[nt], ql[ks], kf[nt >> 1][nt & 1], kf[nt >> 1][(nt & 1) + 2]);
            }
        }

#pragma unroll
        for (int nt = 0; nt < 8; nt++)
#pragma unroll
            for (int c = 0; c < 4; c++) s[nt][c] *= 0.125f;

        // ---- causal mask (diagonal tiles only) ----
        if (kt * 64 + 63 > q0 + wr) {
            const int r0 = q0 + wr + (lane >> 2);
#pragma unroll
            for (int nt = 0; nt < 8; nt++) {
                const int c0 = kt * 64 + nt * 8 + 2 * (lane & 3);
                if (c0 > r0)         s[nt][0] = -1e30f;
                if (c0 + 1 > r0)     s[nt][1] = -1e30f;
                if (c0 > r0 + 8)     s[nt][2] = -1e30f;
                if (c0 + 1 > r0 + 8) s[nt][3] = -1e30f;
            }
        }

        // ---- online softmax (fp32, quad shuffles) ----
        float mx0 = -1e30f, mx1 = -1e30f;
#pragma unroll
        for (int nt = 0; nt < 8; nt++) {
            mx0 = fmaxf(mx0, fmaxf(s[nt][0], s[nt][1]));
            mx1 = fmaxf(mx1, fmaxf(s[nt][2], s[nt][3]));
        }
        mx0 = fmaxf(mx0, __shfl_xor_sync(0xffffffffu, mx0, 1));
        mx0 = fmaxf(mx0, __shfl_xor_sync(0xffffffffu, mx0, 2));
        mx1 = fmaxf(mx1, __shfl_xor_sync(0xffffffffu, mx1, 1));
        mx1 = fmaxf(mx1, __shfl_xor_sync(0xffffffffu, mx1, 2));
        const float n0 = fmaxf(m0, mx0), n1 = fmaxf(m1, mx1);
        const float cr0 = __expf(m0 - n0), cr1 = __expf(m1 - n1);
        m0 = n0; m1 = n1;
        float sum0 = 0.0f, sum1 = 0.0f;
#pragma unroll
        for (int nt = 0; nt < 8; nt++) {
            s[nt][0] = __expf(s[nt][0] - n0); sum0 += s[nt][0];
            s[nt][1] = __expf(s[nt][1] - n0); sum0 += s[nt][1];
            s[nt][2] = __expf(s[nt][2] - n1); sum1 += s[nt][2];
            s[nt][3] = __expf(s[nt][3] - n1); sum1 += s[nt][3];
        }
        sum0 += __shfl_xor_sync(0xffffffffu, sum0, 1);
        sum0 += __shfl_xor_sync(0xffffffffu, sum0, 2);
        sum1 += __shfl_xor_sync(0xffffffffu, sum1, 1);
        sum1 += __shfl_xor_sync(0xffffffffu, sum1, 2);
        l0 = l0 * cr0 + sum0;
        l1 = l1 * cr1 + sum1;
#pragma unroll
        for (int nt = 0; nt < 8; nt++) {
            o[nt][0] *= cr0; o[nt][1] *= cr0;
            o[nt][2] *= cr1; o[nt][3] *= cr1;
        }

        // ---- P fragments (fp16 hi + residual, exact split) ----
        uint32_t ph[4][4], pl[4][4];
#pragma unroll
        for (int ks = 0; ks < 4; ks++) {
            split2h(s[2 * ks][0], s[2 * ks][1], ph[ks][0], pl[ks][0]);
            split2h(s[2 * ks][2], s[2 * ks][3], ph[ks][1], pl[ks][1]);
            split2h(s[2 * ks + 1][0], s[2 * ks + 1][1], ph[ks][2], pl[ks][2]);
            split2h(s[2 * ks + 1][2], s[2 * ks + 1][3], ph[ks][3], pl[ks][3]);
        }

        // ---- O += (ph+pl) V ----
#pragma unroll
        for (int ks = 0; ks < 4; ks++) {
            uint32_t vh[4][4];
#pragma unroll
            for (int ng = 0; ng < 4; ng++) {
                uint32_t a1 = sb + AM_B + (uint32_t)((ks * 16 + lrow) * ALD) * 2 + ng * 32 + lc16;
                LDSM4T(vh[ng][0], vh[ng][1], vh[ng][2], vh[ng][3], a1);
            }
#pragma unroll
            for (int nt = 0; nt < 8; nt++) {
                const uint32_t b0 = vh[nt >> 1][(nt & 1) * 2];
                const uint32_t b1 = vh[nt >> 1][(nt & 1) * 2 + 1];
                MMA_F16(o[nt], ph[ks], b0, b1);
                MMA_F16(o[nt], pl[ks], b0, b1);
            }
        }
    }

    // ---- epilogue: normalize, exact-split to fp16 hi/lo ----
    const float i0 = 1.0f / l0, i1 = 1.0f / l1;
    const size_t r0 = (size_t)(b * SEQ + q0 + wr + (lane >> 2));
    const int colb = h * HDIM + 2 * (lane & 3);
#pragma unroll
    for (int nt = 0; nt < 8; nt++) {
        const int col = colb + nt * 8;
        uint32_t h01, l01;
        split2h(o[nt][0] * i0, o[nt][1] * i0, h01, l01);
        *(uint32_t*)(Ohi + r0 * D_MODEL + col) = h01;
        *(uint32_t*)(Olo + r0 * D_MODEL + col) = l01;
        split2h(o[nt][2] * i1, o[nt][3] * i1, h01, l01);
        *(uint32_t*)(Ohi + (r0 + 8) * D_MODEL + col) = h01;
        *(uint32_t*)(Olo + (r0 + 8) * D_MODEL + col) = l01;
    }
}

// ---------------------------------------------------------------------------
// Launch
// ---------------------------------------------------------------------------
extern "C" void kernel_launch(void* const* d_in, const int* in_sizes, int n_in,
                              void* d_out, int out_size)
{
    (void)in_sizes; (void)n_in; (void)out_size;
    const float* x  = (const float*)d_in[0];
    const float* Wq = (const float*)d_in[1];
    const float* bq = (const float*)d_in[2];
    const float* Wk = (const float*)d_in[3];
    const float* bk = (const float*)d_in[4];
    const float* Wv = (const float*)d_in[5];
    const float* bv = (const float*)d_in[6];
    const float* Wo = (const float*)d_in[7];
    const float* bo = (const float*)d_in[8];
    float* out = (float*)d_out;

    __half *xh, *xl, *wh, *qh, *ql, *kh, *vh, *oh, *ol;
    cudaGetSymbolAddress((void**)&xh, g_xh);
    cudaGetSymbolAddress((void**)&xl, g_xl);
    cudaGetSymbolAddress((void**)&wh, g_wh);
    cudaGetSymbolAddress((void**)&qh, g_qh);
    cudaGetSymbolAddress((void**)&ql, g_ql);
    cudaGetSymbolAddress((void**)&kh, g_kh);
    cudaGetSymbolAddress((void**)&vh, g_vh);
    cudaGetSymbolAddress((void**)&oh, g_oh);
    cudaGetSymbolAddress((void**)&ol, g_ol);

    cudaFuncSetAttribute(attn_mma,
                         cudaFuncAttributeMaxDynamicSharedMemorySize, ATTN_SMEM);
    cudaFuncSetAttribute(gemm_mma<0>,
                         cudaFuncAttributeMaxDynamicSharedMemorySize, GEMM_SMEM);
    cudaFuncSetAttribute(gemm_mma<1>,
                         cudaFuncAttributeMaxDynamicSharedMemorySize, GEMM_SMEM);
    cudaFuncSetAttribute(gemm_mma<2>,
                         cudaFuncAttributeMaxDynamicSharedMemorySize, GEMM_SMEM);

    const int WN = D_MODEL * D_MODEL;
    const int n4x = MTOT * D_MODEL / 4;
    const int n4w = WN / 4;

    split_kernel<<<(n4x + 255) / 256, 256>>>(x, xh, xl, n4x);
    cvt_kernel<<<(n4w + 255) / 256, 256>>>(Wq, wh + 0 * WN, n4w);
    cvt_kernel<<<(n4w + 255) / 256, 256>>>(Wk, wh + 1 * WN, n4w);
    cvt_kernel<<<(n4w + 255) / 256, 256>>>(Wv, wh + 2 * WN, n4w);
    cvt_kernel<<<(n4w + 255) / 256, 256>>>(Wo, wh + 3 * WN, n4w);

    dim3 gGemm(GN / 128, MTOT / 128);          // (8, 32)
    gemm_mma<1><<<gGemm, 256, GEMM_SMEM>>>(xh, xl, wh + 0 * WN, bq,
                                           nullptr, qh, ql);
    gemm_mma<2><<<gGemm, 256, GEMM_SMEM>>>(xh, xl, wh + 1 * WN, bk,
                                           nullptr, kh, nullptr);
    gemm_mma<2><<<gGemm, 256, GEMM_SMEM>>>(xh, xl, wh + 2 * WN, bv,
                                           nullptr, vh, nullptr);

    dim3 gAttn(SEQ / 128, NHEAD, BATCH);       // (16, 16, 2)
    attn_mma<<<gAttn, 256, ATTN_SMEM>>>(qh, ql, kh, vh, oh, ol);

    gemm_mma<0><<<gGemm, 256, GEMM_SMEM>>>(oh, ol, wh + 3 * WN, bo,
                                           out, nullptr, nullptr);
}

// round 7
// speedup vs baseline: 3.2475x; 1.0564x over previous
#include <cuda_runtime.h>
#include <cuda_fp16.h>
#include <cstdint>
#include <cstddef>

#define D_MODEL 1024
#define SEQ     2048
#define BATCH   2
#define NHEAD   16
#define HDIM    64
#define MTOT    (BATCH * SEQ)          // 4096 rows

// ---------------------------------------------------------------------------
// Scratch (no cudaMalloc allowed) — fp16
// ---------------------------------------------------------------------------
__device__ __half g_xh[MTOT * D_MODEL];
__device__ __half g_xl[MTOT * D_MODEL];
__device__ __half g_wh[4 * D_MODEL * D_MODEL];   // Wq|Wk|Wv|Wo rows contiguous
__device__ __half g_qh[MTOT * D_MODEL];
__device__ __half g_ql[MTOT * D_MODEL];
__device__ __half g_kh[MTOT * D_MODEL];
__device__ __half g_vh[MTOT * D_MODEL];
__device__ __half g_oh[MTOT * D_MODEL];
__device__ __half g_ol[MTOT * D_MODEL];

// ---------------------------------------------------------------------------
// PTX helpers (sm_100-safe)
// ---------------------------------------------------------------------------
__device__ __forceinline__ uint32_t smem_u32(const void* p) {
    uint32_t a;
    asm("{ .reg .u64 t; cvta.to.shared.u64 t, %1; cvt.u32.u64 %0, t; }" : "=r"(a) : "l"(p));
    return a;
}
#define CP16(dst, src) \
    asm volatile("cp.async.cg.shared.global [%0], [%1], 16;" :: "r"(dst), "l"(src))
#define CP_COMMIT() asm volatile("cp.async.commit_group;" ::: "memory")
#define CP_WAIT(n)  asm volatile("cp.async.wait_group %0;" :: "n"(n) : "memory")

#define LDSM4(r0, r1, r2, r3, addr) \
    asm volatile("ldmatrix.sync.aligned.m8n8.x4.shared.b16 {%0,%1,%2,%3}, [%4];" \
                 : "=r"(r0), "=r"(r1), "=r"(r2), "=r"(r3) : "r"(addr))
#define LDSM4T(r0, r1, r2, r3, addr) \
    asm volatile("ldmatrix.sync.aligned.m8n8.x4.trans.shared.b16 {%0,%1,%2,%3}, [%4];" \
                 : "=r"(r0), "=r"(r1), "=r"(r2), "=r"(r3) : "r"(addr))

#define MMA_F16(d, a, b0, b1) \
    asm volatile("mma.sync.aligned.m16n8k16.row.col.f32.f16.f16.f32 " \
                 "{%0,%1,%2,%3}, {%4,%5,%6,%7}, {%8,%9}, {%0,%1,%2,%3};" \
                 : "+f"((d)[0]), "+f"((d)[1]), "+f"((d)[2]), "+f"((d)[3]) \
                 : "r"((a)[0]), "r"((a)[1]), "r"((a)[2]), "r"((a)[3]), \
                   "r"(b0), "r"(b1))

// exact fp16 hi + residual split of two fp32 values
__device__ __forceinline__ void split2h(float a, float b, uint32_t& hi, uint32_t& lo) {
    __half2 h = __floats2half2_rn(a, b);
    float ra = a - __half2float(__low2half(h));
    float rb = b - __half2float(__high2half(h));
    __half2 l = __floats2half2_rn(ra, rb);
    hi = *(uint32_t*)&h;
    lo = *(uint32_t*)&l;
}

// ---------------------------------------------------------------------------
// Merged preprocessing: x -> xh+xl split, 4 weights -> fp16 cvt. One launch.
// ---------------------------------------------------------------------------
#define N4X (MTOT * D_MODEL / 4)       // 1048576
#define N4W (D_MODEL * D_MODEL / 4)    // 262144 = 1<<18
#define WN  (D_MODEL * D_MODEL)

__global__ __launch_bounds__(256) void prep_kernel(
    const float* __restrict__ x,
    const float* __restrict__ Wq, const float* __restrict__ Wk,
    const float* __restrict__ Wv, const float* __restrict__ Wo,
    __half* __restrict__ xh, __half* __restrict__ xl, __half* __restrict__ wh)
{
    int i = blockIdx.x * blockDim.x + threadIdx.x;
    if (i < N4X) {
        float4 v = ((const float4*)x)[i];
        uint32_t h0, l0, h1, l1;
        split2h(v.x, v.y, h0, l0);
        split2h(v.z, v.w, h1, l1);
        ((uint32_t*)xh)[2 * i] = h0;  ((uint32_t*)xh)[2 * i + 1] = h1;
        ((uint32_t*)xl)[2 * i] = l0;  ((uint32_t*)xl)[2 * i + 1] = l1;
    } else {
        int t = i - N4X;
        if (t >= 4 * N4W) return;
        int j = t >> 18;
        int w = t & (N4W - 1);
        const float* src = (j == 0) ? Wq : (j == 1) ? Wk : (j == 2) ? Wv : Wo;
        float4 v = ((const float4*)src)[w];
        __half2 a = __floats2half2_rn(v.x, v.y);
        __half2 b = __floats2half2_rn(v.z, v.w);
        __half2* dst = (__half2*)(wh + (size_t)j * WN);
        dst[2 * w] = a;
        dst[2 * w + 1] = b;
    }
}

// ---------------------------------------------------------------------------
// Shared GEMM machinery: 128x128 C tile, BK=32 chunks, A = hi then lo halves
// (split-as-K-extension, 64 chunks), 4-stage cp.async ring, 1 sync/chunk.
// ---------------------------------------------------------------------------
#define GK 1024
#define LDT 40
#define GT_B   (128 * LDT * 2)
#define GST_B  (2 * GT_B)
#define GEMM_SMEM (4 * GST_B)          // 81920 B
#define NCH 64

struct GemmCore {
    uint32_t smb;
    int tid, wid, lane, wr, wc;
    float acc[4][4][4];

    __device__ __forceinline__ void init(uint32_t smb_, int tid_) {
        smb = smb_; tid = tid_;
        wid = tid >> 5; lane = tid & 31;
        wr = (wid & 1) * 64; wc = (wid >> 1) * 32;
#pragma unroll
        for (int mt = 0; mt < 4; mt++)
#pragma unroll
            for (int j = 0; j < 4; j++)
#pragma unroll
                for (int r = 0; r < 4; r++) acc[mt][j][r] = 0.0f;
    }
    __device__ __forceinline__ void load_chunk(
        const __half* __restrict__ Ahi, const __half* __restrict__ Alo,
        const __half* __restrict__ W, int bm, int bn, int c, int stg) {
        const __half* Ap = (c >= 32) ? Alo : Ahi;
        const int k0 = (c & 31) * 32;
        const uint32_t sa = smb + stg * GST_B;
#pragma unroll
        for (int it = 0; it < 2; it++) {
            int idx = tid + it * 256;
            int r = idx >> 2, u = idx & 3;
            CP16(sa + (uint32_t)(r * LDT) * 2 + u * 16,
                 Ap + (size_t)(bm + r) * GK + k0 + u * 8);
        }
#pragma unroll
        for (int it = 0; it < 2; it++) {
            int idx = tid + it * 256;
            int r = idx >> 2, u = idx & 3;
            CP16(sa + GT_B + (uint32_t)(r * LDT) * 2 + u * 16,
                 W + (size_t)(bn + r) * GK + k0 + u * 8);
        }
    }
    __device__ __forceinline__ void compute(int stg) {
        const uint32_t sa = smb + stg * GST_B;
#pragma unroll
        for (int ks = 0; ks < 2; ks++) {
            const int colb = ks * 32 + (lane >> 4) * 16;
            uint32_t a[4][4], b[2][4];
#pragma unroll
            for (int mt = 0; mt < 4; mt++) {
                uint32_t ad = sa + (uint32_t)((wr + mt * 16 + (lane & 15)) * LDT) * 2 + colb;
                LDSM4(a[mt][0], a[mt][1], a[mt][2], a[mt][3], ad);
            }
#pragma unroll
            for (int ng = 0; ng < 2; ng++) {
                uint32_t bd = sa + GT_B + (uint32_t)((wc + ng * 16 + (lane & 15)) * LDT) * 2 + colb;
                LDSM4(b[ng][0], b[ng][1], b[ng][2], b[ng][3], bd);
            }
#pragma unroll
            for (int mt = 0; mt < 4; mt++)
#pragma unroll
                for (int j = 0; j < 4; j++)
                    MMA_F16(acc[mt][j], a[mt], b[j >> 1][j & 1], b[j >> 1][(j & 1) + 2]);
        }
    }
};

// ---------------------------------------------------------------------------
// Fused QKV GEMM: N=3072 over contiguous Wq|Wk|Wv. bn>>10 selects output:
// 0 -> Q (fp16 hi+lo), 1 -> K (hi), 2 -> V (hi).
// ---------------------------------------------------------------------------
__global__ __launch_bounds__(256, 2) void gemm_qkv(
    const __half* __restrict__ Ahi, const __half* __restrict__ Alo,
    const __half* __restrict__ W,
    const float* __restrict__ bq, const float* __restrict__ bk,
    const float* __restrict__ bv,
    __half* __restrict__ Qh, __half* __restrict__ Ql,
    __half* __restrict__ Kh, __half* __restrict__ Vh)
{
    extern __shared__ __align__(128) char smg[];
    GemmCore g;
    g.init(smem_u32(smg), threadIdx.x);
    const int bn = blockIdx.x * 128;            // 0..2944
    const int bm = blockIdx.y * 128;

    g.load_chunk(Ahi, Alo, W, bm, bn, 0, 0); CP_COMMIT();
    g.load_chunk(Ahi, Alo, W, bm, bn, 1, 1); CP_COMMIT();
    g.load_chunk(Ahi, Alo, W, bm, bn, 2, 2); CP_COMMIT();
    for (int c = 0; c < NCH; c++) {
        CP_WAIT(2);
        __syncthreads();
        if (c + 3 < NCH) g.load_chunk(Ahi, Alo, W, bm, bn, c + 3, (c + 3) & 3);
        CP_COMMIT();
        g.compute(c & 3);
    }

    const int bh = bn >> 10;                    // 0:Q 1:K 2:V
    const int cb = bn & 1023;
    const float* bias = (bh == 0) ? bq : (bh == 1) ? bk : bv;
    const int rq = g.lane >> 2;
    const int cq = (g.lane & 3) * 2;
#pragma unroll
    for (int mt = 0; mt < 4; mt++) {
#pragma unroll
        for (int j = 0; j < 4; j++) {
            const int col = cb + g.wc + j * 8 + cq;
            const float b0 = bias[col], b1 = bias[col + 1];
            const int row0 = bm + g.wr + mt * 16 + rq;
            float v0 = g.acc[mt][j][0] + b0, v1 = g.acc[mt][j][1] + b1;
            float v2 = g.acc[mt][j][2] + b0, v3 = g.acc[mt][j][3] + b1;
            if (bh == 0) {
                uint32_t h01, l01;
                split2h(v0, v1, h01, l01);
                *(uint32_t*)(Qh + (size_t)row0 * D_MODEL + col) = h01;
                *(uint32_t*)(Ql + (size_t)row0 * D_MODEL + col) = l01;
                split2h(v2, v3, h01, l01);
                *(uint32_t*)(Qh + (size_t)(row0 + 8) * D_MODEL + col) = h01;
                *(uint32_t*)(Ql + (size_t)(row0 + 8) * D_MODEL + col) = l01;
            } else {
                __half* dst = (bh == 1) ? Kh : Vh;
                *(__half2*)(dst + (size_t)row0 * D_MODEL + col) = __floats2half2_rn(v0, v1);
                *(__half2*)(dst + (size_t)(row0 + 8) * D_MODEL + col) = __floats2half2_rn(v2, v3);
            }
        }
    }
}

// ---------------------------------------------------------------------------
// Output projection GEMM: fp32 out + bias, N=1024.
// ---------------------------------------------------------------------------
__global__ __launch_bounds__(256, 2) void gemm_out(
    const __half* __restrict__ Ahi, const __half* __restrict__ Alo,
    const __half* __restrict__ W,
    const float* __restrict__ bias, float* __restrict__ C)
{
    extern __shared__ __align__(128) char smg[];
    GemmCore g;
    g.init(smem_u32(smg), threadIdx.x);
    const int bn = blockIdx.x * 128;
    const int bm = blockIdx.y * 128;

    g.load_chunk(Ahi, Alo, W, bm, bn, 0, 0); CP_COMMIT();
    g.load_chunk(Ahi, Alo, W, bm, bn, 1, 1); CP_COMMIT();
    g.load_chunk(Ahi, Alo, W, bm, bn, 2, 2); CP_COMMIT();
    for (int c = 0; c < NCH; c++) {
        CP_WAIT(2);
        __syncthreads();
        if (c + 3 < NCH) g.load_chunk(Ahi, Alo, W, bm, bn, c + 3, (c + 3) & 3);
        CP_COMMIT();
        g.compute(c & 3);
    }

    const int rq = g.lane >> 2;
    const int cq = (g.lane & 3) * 2;
#pragma unroll
    for (int mt = 0; mt < 4; mt++) {
#pragma unroll
        for (int j = 0; j < 4; j++) {
            const int col = bn + g.wc + j * 8 + cq;
            const float b0 = bias[col], b1 = bias[col + 1];
            const int row0 = bm + g.wr + mt * 16 + rq;
            *(float2*)(C + (size_t)row0 * D_MODEL + col) =
                make_float2(g.acc[mt][j][0] + b0, g.acc[mt][j][1] + b1);
            *(float2*)(C + (size_t)(row0 + 8) * D_MODEL + col) =
                make_float2(g.acc[mt][j][2] + b0, g.acc[mt][j][3] + b1);
        }
    }
}

// ---------------------------------------------------------------------------
// Flash attention, fp16 mma.sync, causal. 3-stage KV ring, 2 CTAs/SM target.
// Q exact-split; ql fragments reloaded from smem each tile (reg pressure).
// Scale 0.125*log2e absorbed; exp2f softmax.
// ---------------------------------------------------------------------------
#define ALD 72
#define AQ_B  (128 * ALD * 2)          // 18432 B per Q matrix
#define AM_B  (64 * ALD * 2)           // 9216 B per K/V matrix
#define AST_B (2 * AM_B)               // stage: Kh,Vh = 18432 B
#define ATTN_SMEM (2 * AQ_B + 3 * AST_B)   // 92160 B -> 2 CTAs/SM

#define SCL 0.18033688f                // 0.125 * log2(e)

__global__ __launch_bounds__(256, 2) void attn_mma(
    const __half* __restrict__ Qhi, const __half* __restrict__ Qlo,
    const __half* __restrict__ Kh, const __half* __restrict__ Vh,
    __half* __restrict__ Ohi, __half* __restrict__ Olo)
{
    extern __shared__ __align__(128) char smc[];
    const uint32_t smb = smem_u32(smc);
    const int tid = threadIdx.x;
    const int wid = tid >> 5;
    const int lane = tid & 31;
    const int qt = (int)gridDim.x - 1 - (int)blockIdx.x;
    const int h = blockIdx.y, b = blockIdx.z;
    const int q0 = qt * 128;
    const size_t rc0 = (size_t)b * SEQ * D_MODEL + h * HDIM;

    const int wr = wid * 16;
    const uint32_t lrow = lane & 15;
    const uint32_t lc16 = (lane >> 4) * 16;

    auto load_q = [&] {
#pragma unroll
        for (int it = 0; it < 8; it++) {
            int t = tid + it * 256;
            const __half* src = (t < 1024) ? Qhi : Qlo;
            uint32_t moff = (t < 1024) ? 0u : (uint32_t)AQ_B;
            int idx = t & 1023, r = idx >> 3, u = idx & 7;
            CP16(smb + moff + (uint32_t)(r * ALD + u * 8) * 2,
                 src + rc0 + (size_t)(q0 + r) * D_MODEL + u * 8);
        }
    };
    auto load_kv = [&](int kt, int stg) {
        const uint32_t sb = smb + 2 * AQ_B + stg * AST_B;
#pragma unroll
        for (int it = 0; it < 4; it++) {
            int t = tid + it * 256;
            int mtx = t >> 9;                       // 0:Kh 1:Vh
            int idx = t & 511, r = idx >> 3, u = idx & 7;
            const __half* src = (mtx == 0) ? Kh : Vh;
            CP16(sb + mtx * AM_B + (uint32_t)(r * ALD + u * 8) * 2,
                 src + rc0 + (size_t)(kt * 64 + r) * D_MODEL + u * 8);
        }
    };

    float o[8][4];
#pragma unroll
    for (int nt = 0; nt < 8; nt++)
#pragma unroll
        for (int c = 0; c < 4; c++) o[nt][c] = 0.0f;
    float m0 = -1e30f, m1 = -1e30f, l0 = 0.0f, l1 = 0.0f;
    uint32_t qh[4][4];

    const int ktEnd = 2 * qt + 2;
    load_q();
    load_kv(0, 0);
    CP_COMMIT();                       // group 1: Q + kv0
    if (1 < ktEnd) load_kv(1, 1);
    CP_COMMIT();                       // group 2: kv1

    for (int kt = 0; kt < ktEnd; kt++) {
        CP_WAIT(1);
        __syncthreads();
        if (kt + 2 < ktEnd) load_kv(kt + 2, (kt + 2) % 3);
        CP_COMMIT();

        if (kt == 0) {
#pragma unroll
            for (int ks = 0; ks < 4; ks++) {
                uint32_t a1 = smb + (uint32_t)((wr + lrow) * ALD) * 2 + ks * 32 + lc16;
                LDSM4(qh[ks][0], qh[ks][1], qh[ks][2], qh[ks][3], a1);
            }
        }

        const uint32_t sb = smb + 2 * AQ_B + (kt % 3) * AST_B;

        // ---- S = (qh+ql) K^T  (ql reloaded from smem) ----
        float s[8][4];
#pragma unroll
        for (int nt = 0; nt < 8; nt++)
#pragma unroll
            for (int c = 0; c < 4; c++) s[nt][c] = 0.0f;

#pragma unroll
        for (int ks = 0; ks < 4; ks++) {
            uint32_t kf[4][4];
#pragma unroll
            for (int ng = 0; ng < 4; ng++) {
                uint32_t a1 = sb + (uint32_t)((ng * 16 + lrow) * ALD) * 2 + ks * 32 + lc16;
                LDSM4(kf[ng][0], kf[ng][1], kf[ng][2], kf[ng][3], a1);
            }
            uint32_t ql[4];
            uint32_t aq = smb + AQ_B + (uint32_t)((wr + lrow) * ALD) * 2 + ks * 32 + lc16;
            LDSM4(ql[0], ql[1], ql[2], ql[3], aq);
#pragma unroll
            for (int nt = 0; nt < 8; nt++) {
                MMA_F16(s[nt], qh[ks], kf[nt >> 1][nt & 1], kf[nt >> 1][(nt & 1) + 2]);
                MMA_F16(s[nt], ql, kf[nt >> 1][nt & 1], kf[nt >> 1][(nt & 1) + 2]);
            }
        }

#pragma unroll
        for (int nt = 0; nt < 8; nt++)
#pragma unroll
            for (int c = 0; c < 4; c++) s[nt][c] *= SCL;   // log2-domain scores

        // ---- causal mask (diagonal tiles only) ----
        if (kt * 64 + 63 > q0 + wr) {
            const int r0 = q0 + wr + (lane >> 2);
#pragma unroll
            for (int nt = 0; nt < 8; nt++) {
                const int c0 = kt * 64 + nt * 8 + 2 * (lane & 3);
                if (c0 > r0)         s[nt][0] = -1e30f;
                if (c0 + 1 > r0)     s[nt][1] = -1e30f;
                if (c0 > r0 + 8)     s[nt][2] = -1e30f;
                if (c0 + 1 > r0 + 8) s[nt][3] = -1e30f;
            }
        }

        // ---- online softmax (base-2, quad shuffles) ----
        float mx0 = -1e30f, mx1 = -1e30f;
#pragma unroll
        for (int nt = 0; nt < 8; nt++) {
            mx0 = fmaxf(mx0, fmaxf(s[nt][0], s[nt][1]));
            mx1 = fmaxf(mx1, fmaxf(s[nt][2], s[nt][3]));
        }
        mx0 = fmaxf(mx0, __shfl_xor_sync(0xffffffffu, mx0, 1));
        mx0 = fmaxf(mx0, __shfl_xor_sync(0xffffffffu, mx0, 2));
        mx1 = fmaxf(mx1, __shfl_xor_sync(0xffffffffu, mx1, 1));
        mx1 = fmaxf(mx1, __shfl_xor_sync(0xffffffffu, mx1, 2));
        const float n0 = fmaxf(m0, mx0), n1 = fmaxf(m1, mx1);
        const float cr0 = exp2f(m0 - n0), cr1 = exp2f(m1 - n1);
        m0 = n0; m1 = n1;
        float sum0 = 0.0f, sum1 = 0.0f;
#pragma unroll
        for (int nt = 0; nt < 8; nt++) {
            s[nt][0] = exp2f(s[nt][0] - n0); sum0 += s[nt][0];
            s[nt][1] = exp2f(s[nt][1] - n0); sum0 += s[nt][1];
            s[nt][2] = exp2f(s[nt][2] - n1); sum1 += s[nt][2];
            s[nt][3] = exp2f(s[nt][3] - n1); sum1 += s[nt][3];
        }
        sum0 += __shfl_xor_sync(0xffffffffu, sum0, 1);
        sum0 += __shfl_xor_sync(0xffffffffu, sum0, 2);
        sum1 += __shfl_xor_sync(0xffffffffu, sum1, 1);
        sum1 += __shfl_xor_sync(0xffffffffu, sum1, 2);
        l0 = l0 * cr0 + sum0;
        l1 = l1 * cr1 + sum1;
#pragma unroll
        for (int nt = 0; nt < 8; nt++) {
            o[nt][0] *= cr0; o[nt][1] *= cr0;
            o[nt][2] *= cr1; o[nt][3] *= cr1;
        }

        // ---- P fragments (fp16 hi + residual, exact split) ----
        uint32_t ph[4][4], pl[4][4];
#pragma unroll
        for (int ks = 0; ks < 4; ks++) {
            split2h(s[2 * ks][0], s[2 * ks][1], ph[ks][0], pl[ks][0]);
            split2h(s[2 * ks][2], s[2 * ks][3], ph[ks][1], pl[ks][1]);
            split2h(s[2 * ks + 1][0], s[2 * ks + 1][1], ph[ks][2], pl[ks][2]);
            split2h(s[2 * ks + 1][2], s[2 * ks + 1][3], ph[ks][3], pl[ks][3]);
        }

        // ---- O += (ph+pl) V ----
#pragma unroll
        for (int ks = 0; ks < 4; ks++) {
            uint32_t vh[4][4];
#pragma unroll
            for (int ng = 0; ng < 4; ng++) {
                uint32_t a1 = sb + AM_B + (uint32_t)((ks * 16 + lrow) * ALD) * 2 + ng * 32 + lc16;
                LDSM4T(vh[ng][0], vh[ng][1], vh[ng][2], vh[ng][3], a1);
            }
#pragma unroll
            for (int nt = 0; nt < 8; nt++) {
                const uint32_t b0 = vh[nt >> 1][(nt & 1) * 2];
                const uint32_t b1 = vh[nt >> 1][(nt & 1) * 2 + 1];
                MMA_F16(o[nt], ph[ks], b0, b1);
                MMA_F16(o[nt], pl[ks], b0, b1);
            }
        }
    }

    // ---- epilogue: normalize, exact-split to fp16 hi/lo ----
    const float i0 = 1.0f / l0, i1 = 1.0f / l1;
    const size_t r0 = (size_t)(b * SEQ + q0 + wr + (lane >> 2));
    const int colb = h * HDIM + 2 * (lane & 3);
#pragma unroll
    for (int nt = 0; nt < 8; nt++) {
        const int col = colb + nt * 8;
        uint32_t h01, l01;
        split2h(o[nt][0] * i0, o[nt][1] * i0, h01, l01);
        *(uint32_t*)(Ohi + r0 * D_MODEL + col) = h01;
        *(uint32_t*)(Olo + r0 * D_MODEL + col) = l01;
        split2h(o[nt][2] * i1, o[nt][3] * i1, h01, l01);
        *(uint32_t*)(Ohi + (r0 + 8) * D_MODEL + col) = h01;
        *(uint32_t*)(Olo + (r0 + 8) * D_MODEL + col) = l01;
    }
}

// ---------------------------------------------------------------------------
// Launch
// ---------------------------------------------------------------------------
extern "C" void kernel_launch(void* const* d_in, const int* in_sizes, int n_in,
                              void* d_out, int out_size)
{
    (void)in_sizes; (void)n_in; (void)out_size;
    const float* x  = (const float*)d_in[0];
    const float* Wq = (const float*)d_in[1];
    const float* bq = (const float*)d_in[2];
    const float* Wk = (const float*)d_in[3];
    const float* bk = (const float*)d_in[4];
    const float* Wv = (const float*)d_in[5];
    const float* bv = (const float*)d_in[6];
    const float* Wo = (const float*)d_in[7];
    const float* bo = (const float*)d_in[8];
    float* out = (float*)d_out;

    __half *xh, *xl, *wh, *qh, *ql, *kh, *vh, *oh, *ol;
    cudaGetSymbolAddress((void**)&xh, g_xh);
    cudaGetSymbolAddress((void**)&xl, g_xl);
    cudaGetSymbolAddress((void**)&wh, g_wh);
    cudaGetSymbolAddress((void**)&qh, g_qh);
    cudaGetSymbolAddress((void**)&ql, g_ql);
    cudaGetSymbolAddress((void**)&kh, g_kh);
    cudaGetSymbolAddress((void**)&vh, g_vh);
    cudaGetSymbolAddress((void**)&oh, g_oh);
    cudaGetSymbolAddress((void**)&ol, g_ol);

    cudaFuncSetAttribute(attn_mma,
                         cudaFuncAttributeMaxDynamicSharedMemorySize, ATTN_SMEM);
    cudaFuncSetAttribute(gemm_qkv,
                         cudaFuncAttributeMaxDynamicSharedMemorySize, GEMM_SMEM);
    cudaFuncSetAttribute(gemm_out,
                         cudaFuncAttributeMaxDynamicSharedMemorySize, GEMM_SMEM);

    const int nPrep = N4X + 4 * N4W;
    prep_kernel<<<(nPrep + 255) / 256, 256>>>(x, Wq, Wk, Wv, Wo, xh, xl, wh);

    dim3 gQKV(3 * D_MODEL / 128, MTOT / 128);   // (24, 32)
    gemm_qkv<<<gQKV, 256, GEMM_SMEM>>>(xh, xl, wh, bq, bk, bv, qh, ql, kh, vh);

    dim3 gAttn(SEQ / 128, NHEAD, BATCH);        // (16, 16, 2)
    attn_mma<<<gAttn, 256, ATTN_SMEM>>>(qh, ql, kh, vh, oh, ol);

    dim3 gOut(D_MODEL / 128, MTOT / 128);       // (8, 32)
    gemm_out<<<gOut, 256, GEMM_SMEM>>>(oh, ol, wh + (size_t)3 * WN, bo, out);
}

// round 8
// speedup vs baseline: 3.6916x; 1.1368x over previous
#include <cuda_runtime.h>
#include <cuda_fp16.h>
#include <cstdint>
#include <cstddef>

#define D_MODEL 1024
#define SEQ     2048
#define BATCH   2
#define NHEAD   16
#define HDIM    64
#define MTOT    (BATCH * SEQ)          // 4096 rows

// ---------------------------------------------------------------------------
// Scratch (no cudaMalloc allowed) — fp16
// ---------------------------------------------------------------------------
__device__ __half g_xh[MTOT * D_MODEL];
__device__ __half g_xl[MTOT * D_MODEL];
__device__ __half g_wh[4 * D_MODEL * D_MODEL];   // Wq|Wk|Wv|Wo rows contiguous
__device__ __half g_qh[MTOT * D_MODEL];
__device__ __half g_ql[MTOT * D_MODEL];
__device__ __half g_kh[MTOT * D_MODEL];
__device__ __half g_vh[MTOT * D_MODEL];
__device__ __half g_oh[MTOT * D_MODEL];
__device__ __half g_ol[MTOT * D_MODEL];

// ---------------------------------------------------------------------------
// PTX helpers (sm_100-safe)
// ---------------------------------------------------------------------------
__device__ __forceinline__ uint32_t smem_u32(const void* p) {
    uint32_t a;
    asm("{ .reg .u64 t; cvta.to.shared.u64 t, %1; cvt.u32.u64 %0, t; }" : "=r"(a) : "l"(p));
    return a;
}
#define CP16(dst, src) \
    asm volatile("cp.async.cg.shared.global [%0], [%1], 16;" :: "r"(dst), "l"(src))
#define CP_COMMIT() asm volatile("cp.async.commit_group;" ::: "memory")
#define CP_WAIT(n)  asm volatile("cp.async.wait_group %0;" :: "n"(n) : "memory")

#define LDSM4(r0, r1, r2, r3, addr) \
    asm volatile("ldmatrix.sync.aligned.m8n8.x4.shared.b16 {%0,%1,%2,%3}, [%4];" \
                 : "=r"(r0), "=r"(r1), "=r"(r2), "=r"(r3) : "r"(addr))
#define LDSM4T(r0, r1, r2, r3, addr) \
    asm volatile("ldmatrix.sync.aligned.m8n8.x4.trans.shared.b16 {%0,%1,%2,%3}, [%4];" \
                 : "=r"(r0), "=r"(r1), "=r"(r2), "=r"(r3) : "r"(addr))

#define MMA_F16(d, a, b0, b1) \
    asm volatile("mma.sync.aligned.m16n8k16.row.col.f32.f16.f16.f32 " \
                 "{%0,%1,%2,%3}, {%4,%5,%6,%7}, {%8,%9}, {%0,%1,%2,%3};" \
                 : "+f"((d)[0]), "+f"((d)[1]), "+f"((d)[2]), "+f"((d)[3]) \
                 : "r"((a)[0]), "r"((a)[1]), "r"((a)[2]), "r"((a)[3]), \
                   "r"(b0), "r"(b1))

// exact fp16 hi + residual split of two fp32 values
__device__ __forceinline__ void split2h(float a, float b, uint32_t& hi, uint32_t& lo) {
    __half2 h = __floats2half2_rn(a, b);
    float ra = a - __half2float(__low2half(h));
    float rb = b - __half2float(__high2half(h));
    __half2 l = __floats2half2_rn(ra, rb);
    hi = *(uint32_t*)&h;
    lo = *(uint32_t*)&l;
}

// ---------------------------------------------------------------------------
// Merged preprocessing: x -> xh+xl split, 4 weights -> fp16 cvt. One launch.
// ---------------------------------------------------------------------------
#define N4X (MTOT * D_MODEL / 4)       // 1048576
#define N4W (D_MODEL * D_MODEL / 4)    // 262144 = 1<<18
#define WN  (D_MODEL * D_MODEL)

__global__ __launch_bounds__(256) void prep_kernel(
    const float* __restrict__ x,
    const float* __restrict__ Wq, const float* __restrict__ Wk,
    const float* __restrict__ Wv, const float* __restrict__ Wo,
    __half* __restrict__ xh, __half* __restrict__ xl, __half* __restrict__ wh)
{
    int i = blockIdx.x * blockDim.x + threadIdx.x;
    if (i < N4X) {
        float4 v = ((const float4*)x)[i];
        uint32_t h0, l0, h1, l1;
        split2h(v.x, v.y, h0, l0);
        split2h(v.z, v.w, h1, l1);
        ((uint32_t*)xh)[2 * i] = h0;  ((uint32_t*)xh)[2 * i + 1] = h1;
        ((uint32_t*)xl)[2 * i] = l0;  ((uint32_t*)xl)[2 * i + 1] = l1;
    } else {
        int t = i - N4X;
        if (t >= 4 * N4W) return;
        int j = t >> 18;
        int w = t & (N4W - 1);
        const float* src = (j == 0) ? Wq : (j == 1) ? Wk : (j == 2) ? Wv : Wo;
        float4 v = ((const float4*)src)[w];
        __half2 a = __floats2half2_rn(v.x, v.y);
        __half2 b = __floats2half2_rn(v.z, v.w);
        __half2* dst = (__half2*)(wh + (size_t)j * WN);
        dst[2 * w] = a;
        dst[2 * w + 1] = b;
    }
}

// ---------------------------------------------------------------------------
// GEMM core: 128x128 C tile, BK=64 chunks (32 chunks: hi half then lo half),
// 3-stage cp.async ring, ONE __syncthreads per 64-K chunk.
// ---------------------------------------------------------------------------
#define GK 1024
#define GLD 72                          // row stride in fp16 (144 B, conflict-free)
#define GTB  (128 * GLD * 2)            // 18432 B per matrix tile
#define GSTB (2 * GTB)                  // 36864 B per stage (A + B)
#define GEMM_SMEM (3 * GSTB)            // 110592 B -> 2 CTAs/SM
#define NCH 32

struct GemmCore {
    uint32_t smb;
    int tid, wid, lane, wr, wc;
    float acc[4][4][4];

    __device__ __forceinline__ void init(uint32_t smb_, int tid_) {
        smb = smb_; tid = tid_;
        wid = tid >> 5; lane = tid & 31;
        wr = (wid & 1) * 64; wc = (wid >> 1) * 32;
#pragma unroll
        for (int mt = 0; mt < 4; mt++)
#pragma unroll
            for (int j = 0; j < 4; j++)
#pragma unroll
                for (int r = 0; r < 4; r++) acc[mt][j][r] = 0.0f;
    }
    __device__ __forceinline__ void load_chunk(
        const __half* __restrict__ Ahi, const __half* __restrict__ Alo,
        const __half* __restrict__ W, int bm, int bn, int c, int stg) {
        const __half* Ap = (c >= 16) ? Alo : Ahi;
        const int k0 = (c & 15) * 64;
        const uint32_t sa = smb + stg * GSTB;
#pragma unroll
        for (int it = 0; it < 4; it++) {
            int idx = tid + it * 256;          // 0..1023
            int r = idx >> 3, u = idx & 7;
            CP16(sa + (uint32_t)(r * GLD) * 2 + u * 16,
                 Ap + (size_t)(bm + r) * GK + k0 + u * 8);
        }
#pragma unroll
        for (int it = 0; it < 4; it++) {
            int idx = tid + it * 256;
            int r = idx >> 3, u = idx & 7;
            CP16(sa + GTB + (uint32_t)(r * GLD) * 2 + u * 16,
                 W + (size_t)(bn + r) * GK + k0 + u * 8);
        }
    }
    __device__ __forceinline__ void compute(int stg) {
        const uint32_t sa = smb + stg * GSTB;
#pragma unroll
        for (int ks = 0; ks < 4; ks++) {
            const int colb = ks * 32 + (lane >> 4) * 16;
            uint32_t a[4][4], b[2][4];
#pragma unroll
            for (int mt = 0; mt < 4; mt++) {
                uint32_t ad = sa + (uint32_t)((wr + mt * 16 + (lane & 15)) * GLD) * 2 + colb;
                LDSM4(a[mt][0], a[mt][1], a[mt][2], a[mt][3], ad);
            }
#pragma unroll
            for (int ng = 0; ng < 2; ng++) {
                uint32_t bd = sa + GTB + (uint32_t)((wc + ng * 16 + (lane & 15)) * GLD) * 2 + colb;
                LDSM4(b[ng][0], b[ng][1], b[ng][2], b[ng][3], bd);
            }
#pragma unroll
            for (int mt = 0; mt < 4; mt++)
#pragma unroll
                for (int j = 0; j < 4; j++)
                    MMA_F16(acc[mt][j], a[mt], b[j >> 1][j & 1], b[j >> 1][(j & 1) + 2]);
        }
    }
    // mainloop: 3-stage ring, chunk c is group c+1, WAIT(1) completes it
    __device__ __forceinline__ void run(
        const __half* __restrict__ Ahi, const __half* __restrict__ Alo,
        const __half* __restrict__ W, int bm, int bn) {
        load_chunk(Ahi, Alo, W, bm, bn, 0, 0); CP_COMMIT();
        load_chunk(Ahi, Alo, W, bm, bn, 1, 1); CP_COMMIT();
        for (int c = 0; c < NCH; c++) {
            CP_WAIT(1);
            __syncthreads();
            if (c + 2 < NCH) load_chunk(Ahi, Alo, W, bm, bn, c + 2, (c + 2) % 3);
            CP_COMMIT();
            compute(c % 3);
        }
    }
};

// ---------------------------------------------------------------------------
// Fused QKV GEMM: N=3072 over contiguous Wq|Wk|Wv. bn>>10 selects output:
// 0 -> Q (fp16 hi+lo), 1 -> K (hi), 2 -> V (hi).
// ---------------------------------------------------------------------------
__global__ __launch_bounds__(256, 2) void gemm_qkv(
    const __half* __restrict__ Ahi, const __half* __restrict__ Alo,
    const __half* __restrict__ W,
    const float* __restrict__ bq, const float* __restrict__ bk,
    const float* __restrict__ bv,
    __half* __restrict__ Qh, __half* __restrict__ Ql,
    __half* __restrict__ Kh, __half* __restrict__ Vh)
{
    extern __shared__ __align__(128) char smg[];
    GemmCore g;
    g.init(smem_u32(smg), threadIdx.x);
    const int bn = blockIdx.x * 128;            // 0..2944
    const int bm = blockIdx.y * 128;
    g.run(Ahi, Alo, W, bm, bn);

    const int bh = bn >> 10;                    // 0:Q 1:K 2:V
    const int cb = bn & 1023;
    const float* bias = (bh == 0) ? bq : (bh == 1) ? bk : bv;
    const int rq = g.lane >> 2;
    const int cq = (g.lane & 3) * 2;
#pragma unroll
    for (int mt = 0; mt < 4; mt++) {
#pragma unroll
        for (int j = 0; j < 4; j++) {
            const int col = cb + g.wc + j * 8 + cq;
            const float b0 = bias[col], b1 = bias[col + 1];
            const int row0 = bm + g.wr + mt * 16 + rq;
            float v0 = g.acc[mt][j][0] + b0, v1 = g.acc[mt][j][1] + b1;
            float v2 = g.acc[mt][j][2] + b0, v3 = g.acc[mt][j][3] + b1;
            if (bh == 0) {
                uint32_t h01, l01;
                split2h(v0, v1, h01, l01);
                *(uint32_t*)(Qh + (size_t)row0 * D_MODEL + col) = h01;
                *(uint32_t*)(Ql + (size_t)row0 * D_MODEL + col) = l01;
                split2h(v2, v3, h01, l01);
                *(uint32_t*)(Qh + (size_t)(row0 + 8) * D_MODEL + col) = h01;
                *(uint32_t*)(Ql + (size_t)(row0 + 8) * D_MODEL + col) = l01;
            } else {
                __half* dst = (bh == 1) ? Kh : Vh;
                *(__half2*)(dst + (size_t)row0 * D_MODEL + col) = __floats2half2_rn(v0, v1);
                *(__half2*)(dst + (size_t)(row0 + 8) * D_MODEL + col) = __floats2half2_rn(v2, v3);
            }
        }
    }
}

// ---------------------------------------------------------------------------
// Output projection GEMM: fp32 out + bias, N=1024.
// ---------------------------------------------------------------------------
__global__ __launch_bounds__(256, 2) void gemm_out(
    const __half* __restrict__ Ahi, const __half* __restrict__ Alo,
    const __half* __restrict__ W,
    const float* __restrict__ bias, float* __restrict__ C)
{
    extern __shared__ __align__(128) char smg[];
    GemmCore g;
    g.init(smem_u32(smg), threadIdx.x);
    const int bn = blockIdx.x * 128;
    const int bm = blockIdx.y * 128;
    g.run(Ahi, Alo, W, bm, bn);

    const int rq = g.lane >> 2;
    const int cq = (g.lane & 3) * 2;
#pragma unroll
    for (int mt = 0; mt < 4; mt++) {
#pragma unroll
        for (int j = 0; j < 4; j++) {
            const int col = bn + g.wc + j * 8 + cq;
            const float b0 = bias[col], b1 = bias[col + 1];
            const int row0 = bm + g.wr + mt * 16 + rq;
            *(float2*)(C + (size_t)row0 * D_MODEL + col) =
                make_float2(g.acc[mt][j][0] + b0, g.acc[mt][j][1] + b1);
            *(float2*)(C + (size_t)(row0 + 8) * D_MODEL + col) =
                make_float2(g.acc[mt][j][2] + b0, g.acc[mt][j][3] + b1);
        }
    }
}

// ---------------------------------------------------------------------------
// Flash attention, fp16 mma.sync, causal. Q-tile PAIRING for load balance:
// grid.x = 8; CTA bx handles qt = 8+bx (long) then qt = 7-bx (short):
// every CTA does exactly 34 KV iterations -> one balanced wave (256 CTAs).
// 3-stage KV ring, 2 CTAs/SM.
// ---------------------------------------------------------------------------
#define ALD 72
#define AQ_B  (128 * ALD * 2)          // 18432 B per Q matrix
#define AM_B  (64 * ALD * 2)           // 9216 B per K/V matrix
#define AST_B (2 * AM_B)               // stage: Kh,Vh = 18432 B
#define ATTN_SMEM (2 * AQ_B + 3 * AST_B)   // 92160 B -> 2 CTAs/SM

#define SCL 0.18033688f                // 0.125 * log2(e)

__global__ __launch_bounds__(256, 2) void attn_mma(
    const __half* __restrict__ Qhi, const __half* __restrict__ Qlo,
    const __half* __restrict__ Kh, const __half* __restrict__ Vh,
    __half* __restrict__ Ohi, __half* __restrict__ Olo)
{
    extern __shared__ __align__(128) char smc[];
    const uint32_t smb = smem_u32(smc);
    const int tid = threadIdx.x;
    const int wid = tid >> 5;
    const int lane = tid & 31;
    const int bx = blockIdx.x;
    const int h = blockIdx.y, b = blockIdx.z;
    const size_t rc0 = (size_t)b * SEQ * D_MODEL + h * HDIM;

    const int wr = wid * 16;
    const uint32_t lrow = lane & 15;
    const uint32_t lc16 = (lane >> 4) * 16;

    auto load_q = [&](int q0) {
#pragma unroll
        for (int it = 0; it < 8; it++) {
            int t = tid + it * 256;
            const __half* src = (t < 1024) ? Qhi : Qlo;
            uint32_t moff = (t < 1024) ? 0u : (uint32_t)AQ_B;
            int idx = t & 1023, r = idx >> 3, u = idx & 7;
            CP16(smb + moff + (uint32_t)(r * ALD + u * 8) * 2,
                 src + rc0 + (size_t)(q0 + r) * D_MODEL + u * 8);
        }
    };
    auto load_kv = [&](int kt, int stg) {
        const uint32_t sb = smb + 2 * AQ_B + stg * AST_B;
#pragma unroll
        for (int it = 0; it < 4; it++) {
            int t = tid + it * 256;
            int mtx = t >> 9;                       // 0:Kh 1:Vh
            int idx = t & 511, r = idx >> 3, u = idx & 7;
            const __half* src = (mtx == 0) ? Kh : Vh;
            CP16(sb + mtx * AM_B + (uint32_t)(r * ALD + u * 8) * 2,
                 src + rc0 + (size_t)(kt * 64 + r) * D_MODEL + u * 8);
        }
    };

    for (int half = 0; half < 2; half++) {
        const int qt = half ? (7 - bx) : (8 + bx);
        const int q0 = qt * 128;
        const int ktEnd = 2 * qt + 2;

        float o[8][4];
#pragma unroll
        for (int nt = 0; nt < 8; nt++)
#pragma unroll
            for (int c = 0; c < 4; c++) o[nt][c] = 0.0f;
        float m0 = -1e30f, m1 = -1e30f, l0 = 0.0f, l1 = 0.0f;
        uint32_t qh[4][4];

        load_q(q0);
        load_kv(0, 0);
        CP_COMMIT();                       // group: Q + kv0
        if (1 < ktEnd) load_kv(1, 1);
        CP_COMMIT();                       // group: kv1

        for (int kt = 0; kt < ktEnd; kt++) {
            CP_WAIT(1);
            __syncthreads();
            if (kt + 2 < ktEnd) load_kv(kt + 2, (kt + 2) % 3);
            CP_COMMIT();

            if (kt == 0) {
#pragma unroll
                for (int ks = 0; ks < 4; ks++) {
                    uint32_t a1 = smb + (uint32_t)((wr + lrow) * ALD) * 2 + ks * 32 + lc16;
                    LDSM4(qh[ks][0], qh[ks][1], qh[ks][2], qh[ks][3], a1);
                }
            }

            const uint32_t sb = smb + 2 * AQ_B + (kt % 3) * AST_B;

            // ---- S = (qh+ql) K^T  (ql reloaded from smem) ----
            float s[8][4];
#pragma unroll
            for (int nt = 0; nt < 8; nt++)
#pragma unroll
                for (int c = 0; c < 4; c++) s[nt][c] = 0.0f;

#pragma unroll
            for (int ks = 0; ks < 4; ks++) {
                uint32_t kf[4][4];
#pragma unroll
                for (int ng = 0; ng < 4; ng++) {
                    uint32_t a1 = sb + (uint32_t)((ng * 16 + lrow) * ALD) * 2 + ks * 32 + lc16;
                    LDSM4(kf[ng][0], kf[ng][1], kf[ng][2], kf[ng][3], a1);
                }
                uint32_t ql[4];
                uint32_t aq = smb + AQ_B + (uint32_t)((wr + lrow) * ALD) * 2 + ks * 32 + lc16;
                LDSM4(ql[0], ql[1], ql[2], ql[3], aq);
#pragma unroll
                for (int nt = 0; nt < 8; nt++) {
                    MMA_F16(s[nt], qh[ks], kf[nt >> 1][nt & 1], kf[nt >> 1][(nt & 1) + 2]);
                    MMA_F16(s[nt], ql, kf[nt >> 1][nt & 1], kf[nt >> 1][(nt & 1) + 2]);
                }
            }

#pragma unroll
            for (int nt = 0; nt < 8; nt++)
#pragma unroll
                for (int c = 0; c < 4; c++) s[nt][c] *= SCL;   // log2-domain

            // ---- causal mask (diagonal tiles only) ----
            if (kt * 64 + 63 > q0 + wr) {
                const int r0 = q0 + wr + (lane >> 2);
#pragma unroll
                for (int nt = 0; nt < 8; nt++) {
                    const int c0 = kt * 64 + nt * 8 + 2 * (lane & 3);
                    if (c0 > r0)         s[nt][0] = -1e30f;
                    if (c0 + 1 > r0)     s[nt][1] = -1e30f;
                    if (c0 > r0 + 8)     s[nt][2] = -1e30f;
                    if (c0 + 1 > r0 + 8) s[nt][3] = -1e30f;
                }
            }

            // ---- online softmax (base-2, quad shuffles) ----
            float mx0 = -1e30f, mx1 = -1e30f;
#pragma unroll
            for (int nt = 0; nt < 8; nt++) {
                mx0 = fmaxf(mx0, fmaxf(s[nt][0], s[nt][1]));
                mx1 = fmaxf(mx1, fmaxf(s[nt][2], s[nt][3]));
            }
            mx0 = fmaxf(mx0, __shfl_xor_sync(0xffffffffu, mx0, 1));
            mx0 = fmaxf(mx0, __shfl_xor_sync(0xffffffffu, mx0, 2));
            mx1 = fmaxf(mx1, __shfl_xor_sync(0xffffffffu, mx1, 1));
            mx1 = fmaxf(mx1, __shfl_xor_sync(0xffffffffu, mx1, 2));
            const float n0 = fmaxf(m0, mx0), n1 = fmaxf(m1, mx1);
            const float cr0 = exp2f(m0 - n0), cr1 = exp2f(m1 - n1);
            m0 = n0; m1 = n1;
            float sum0 = 0.0f, sum1 = 0.0f;
#pragma unroll
            for (int nt = 0; nt < 8; nt++) {
                s[nt][0] = exp2f(s[nt][0] - n0); sum0 += s[nt][0];
                s[nt][1] = exp2f(s[nt][1] - n0); sum0 += s[nt][1];
                s[nt][2] = exp2f(s[nt][2] - n1); sum1 += s[nt][2];
                s[nt][3] = exp2f(s[nt][3] - n1); sum1 += s[nt][3];
            }
            sum0 += __shfl_xor_sync(0xffffffffu, sum0, 1);
            sum0 += __shfl_xor_sync(0xffffffffu, sum0, 2);
            sum1 += __shfl_xor_sync(0xffffffffu, sum1, 1);
            sum1 += __shfl_xor_sync(0xffffffffu, sum1, 2);
            l0 = l0 * cr0 + sum0;
            l1 = l1 * cr1 + sum1;
#pragma unroll
            for (int nt = 0; nt < 8; nt++) {
                o[nt][0] *= cr0; o[nt][1] *= cr0;
                o[nt][2] *= cr1; o[nt][3] *= cr1;
            }

            // ---- P fragments (fp16 hi + residual, exact split) ----
            uint32_t ph[4][4], pl[4][4];
#pragma unroll
            for (int ks = 0; ks < 4; ks++) {
                split2h(s[2 * ks][0], s[2 * ks][1], ph[ks][0], pl[ks][0]);
                split2h(s[2 * ks][2], s[2 * ks][3], ph[ks][1], pl[ks][1]);
                split2h(s[2 * ks + 1][0], s[2 * ks + 1][1], ph[ks][2], pl[ks][2]);
                split2h(s[2 * ks + 1][2], s[2 * ks + 1][3], ph[ks][3], pl[ks][3]);
            }

            // ---- O += (ph+pl) V ----
#pragma unroll
            for (int ks = 0; ks < 4; ks++) {
                uint32_t vh[4][4];
#pragma unroll
                for (int ng = 0; ng < 4; ng++) {
                    uint32_t a1 = sb + AM_B + (uint32_t)((ks * 16 + lrow) * ALD) * 2 + ng * 32 + lc16;
                    LDSM4T(vh[ng][0], vh[ng][1], vh[ng][2], vh[ng][3], a1);
                }
#pragma unroll
                for (int nt = 0; nt < 8; nt++) {
                    const uint32_t b0 = vh[nt >> 1][(nt & 1) * 2];
                    const uint32_t b1 = vh[nt >> 1][(nt & 1) * 2 + 1];
                    MMA_F16(o[nt], ph[ks], b0, b1);
                    MMA_F16(o[nt], pl[ks], b0, b1);
                }
            }
        }

        // ---- epilogue: normalize, exact-split to fp16 hi/lo ----
        const float i0 = 1.0f / l0, i1 = 1.0f / l1;
        const size_t r0 = (size_t)(b * SEQ + q0 + wr + (lane >> 2));
        const int colb = h * HDIM + 2 * (lane & 3);
#pragma unroll
        for (int nt = 0; nt < 8; nt++) {
            const int col = colb + nt * 8;
            uint32_t h01, l01;
            split2h(o[nt][0] * i0, o[nt][1] * i0, h01, l01);
            *(uint32_t*)(Ohi + r0 * D_MODEL + col) = h01;
            *(uint32_t*)(Olo + r0 * D_MODEL + col) = l01;
            split2h(o[nt][2] * i1, o[nt][3] * i1, h01, l01);
            *(uint32_t*)(Ohi + (r0 + 8) * D_MODEL + col) = h01;
            *(uint32_t*)(Olo + (r0 + 8) * D_MODEL + col) = l01;
        }

        // drain before next tile reuses Q/KV smem
        CP_WAIT(0);
        __syncthreads();
    }
}

// ---------------------------------------------------------------------------
// Launch
// ---------------------------------------------------------------------------
extern "C" void kernel_launch(void* const* d_in, const int* in_sizes, int n_in,
                              void* d_out, int out_size)
{
    (void)in_sizes; (void)n_in; (void)out_size;
    const float* x  = (const float*)d_in[0];
    const float* Wq = (const float*)d_in[1];
    const float* bq = (const float*)d_in[2];
    const float* Wk = (const float*)d_in[3];
    const float* bk = (const float*)d_in[4];
    const float* Wv = (const float*)d_in[5];
    const float* bv = (const float*)d_in[6];
    const float* Wo = (const float*)d_in[7];
    const float* bo = (const float*)d_in[8];
    float* out = (float*)d_out;

    __half *xh, *xl, *wh, *qh, *ql, *kh, *vh, *oh, *ol;
    cudaGetSymbolAddress((void**)&xh, g_xh);
    cudaGetSymbolAddress((void**)&xl, g_xl);
    cudaGetSymbolAddress((void**)&wh, g_wh);
    cudaGetSymbolAddress((void**)&qh, g_qh);
    cudaGetSymbolAddress((void**)&ql, g_ql);
    cudaGetSymbolAddress((void**)&kh, g_kh);
    cudaGetSymbolAddress((void**)&vh, g_vh);
    cudaGetSymbolAddress((void**)&oh, g_oh);
    cudaGetSymbolAddress((void**)&ol, g_ol);

    cudaFuncSetAttribute(attn_mma,
                         cudaFuncAttributeMaxDynamicSharedMemorySize, ATTN_SMEM);
    cudaFuncSetAttribute(gemm_qkv,
                         cudaFuncAttributeMaxDynamicSharedMemorySize, GEMM_SMEM);
    cudaFuncSetAttribute(gemm_out,
                         cudaFuncAttributeMaxDynamicSharedMemorySize, GEMM_SMEM);

    const int nPrep = N4X + 4 * N4W;
    prep_kernel<<<(nPrep + 255) / 256, 256>>>(x, Wq, Wk, Wv, Wo, xh, xl, wh);

    dim3 gQKV(3 * D_MODEL / 128, MTOT / 128);   // (24, 32)
    gemm_qkv<<<gQKV, 256, GEMM_SMEM>>>(xh, xl, wh, bq, bk, bv, qh, ql, kh, vh);

    dim3 gAttn(SEQ / 256, NHEAD, BATCH);        // (8, 16, 2) - paired tiles
    attn_mma<<<gAttn, 256, ATTN_SMEM>>>(qh, ql, kh, vh, oh, ol);

    dim3 gOut(D_MODEL / 128, MTOT / 128);       // (8, 32)
    gemm_out<<<gOut, 256, GEMM_SMEM>>>(oh, ol, wh + (size_t)3 * WN, bo, out);
}

// round 9
// speedup vs baseline: 3.9915x; 1.0812x over previous
#include <cuda_runtime.h>
#include <cuda_fp16.h>
#include <cstdint>
#include <cstddef>

#define D_MODEL 1024
#define SEQ     2048
#define BATCH   2
#define NHEAD   16
#define HDIM    64
#define MTOT    (BATCH * SEQ)          // 4096 rows

// ---------------------------------------------------------------------------
// Scratch (no cudaMalloc allowed) — fp16
// ---------------------------------------------------------------------------
__device__ __half g_xh[MTOT * D_MODEL];
__device__ __half g_xl[MTOT * D_MODEL];
__device__ __half g_wh[4 * D_MODEL * D_MODEL];   // Wq|Wk|Wv|Wo rows contiguous
__device__ __half g_qh[MTOT * D_MODEL];
__device__ __half g_ql[MTOT * D_MODEL];
__device__ __half g_kh[MTOT * D_MODEL];
__device__ __half g_vh[MTOT * D_MODEL];
__device__ __half g_oh[MTOT * D_MODEL];
__device__ __half g_ol[MTOT * D_MODEL];

// ---------------------------------------------------------------------------
// PTX helpers (sm_100-safe)
// ---------------------------------------------------------------------------
__device__ __forceinline__ uint32_t smem_u32(const void* p) {
    uint32_t a;
    asm("{ .reg .u64 t; cvta.to.shared.u64 t, %1; cvt.u32.u64 %0, t; }" : "=r"(a) : "l"(p));
    return a;
}
#define CP16(dst, src) \
    asm volatile("cp.async.cg.shared.global [%0], [%1], 16;" :: "r"(dst), "l"(src))
#define CP_COMMIT() asm volatile("cp.async.commit_group;" ::: "memory")
#define CP_WAIT(n)  asm volatile("cp.async.wait_group %0;" :: "n"(n) : "memory")

#define LDSM4(r0, r1, r2, r3, addr) \
    asm volatile("ldmatrix.sync.aligned.m8n8.x4.shared.b16 {%0,%1,%2,%3}, [%4];" \
                 : "=r"(r0), "=r"(r1), "=r"(r2), "=r"(r3) : "r"(addr))
#define LDSM4T(r0, r1, r2, r3, addr) \
    asm volatile("ldmatrix.sync.aligned.m8n8.x4.trans.shared.b16 {%0,%1,%2,%3}, [%4];" \
                 : "=r"(r0), "=r"(r1), "=r"(r2), "=r"(r3) : "r"(addr))

#define MMA_F16(d, a, b0, b1) \
    asm volatile("mma.sync.aligned.m16n8k16.row.col.f32.f16.f16.f32 " \
                 "{%0,%1,%2,%3}, {%4,%5,%6,%7}, {%8,%9}, {%0,%1,%2,%3};" \
                 : "+f"((d)[0]), "+f"((d)[1]), "+f"((d)[2]), "+f"((d)[3]) \
                 : "r"((a)[0]), "r"((a)[1]), "r"((a)[2]), "r"((a)[3]), \
                   "r"(b0), "r"(b1))

// exact fp16 hi + residual split of two fp32 values
__device__ __forceinline__ void split2h(float a, float b, uint32_t& hi, uint32_t& lo) {
    __half2 h = __floats2half2_rn(a, b);
    float ra = a - __half2float(__low2half(h));
    float rb = b - __half2float(__high2half(h));
    __half2 l = __floats2half2_rn(ra, rb);
    hi = *(uint32_t*)&h;
    lo = *(uint32_t*)&l;
}
__device__ __forceinline__ uint32_t pack2h(float a, float b) {
    __half2 h = __floats2half2_rn(a, b);
    return *(uint32_t*)&h;
}

// ---------------------------------------------------------------------------
// Merged preprocessing, 4 strided float4s per thread (MLP=4).
// ---------------------------------------------------------------------------
#define N4X (MTOT * D_MODEL / 4)       // 1048576
#define N4W (D_MODEL * D_MODEL / 4)    // 262144 = 1<<18
#define WN  (D_MODEL * D_MODEL)
#define NPREP (N4X + 4 * N4W)          // 2097152
#define PREP_BLOCKS (NPREP / (256 * 4))  // 2048

__global__ __launch_bounds__(256) void prep_kernel(
    const float* __restrict__ x,
    const float* __restrict__ Wq, const float* __restrict__ Wk,
    const float* __restrict__ Wv, const float* __restrict__ Wo,
    __half* __restrict__ xh, __half* __restrict__ xl, __half* __restrict__ wh)
{
    const int stride = PREP_BLOCKS * 256;
#pragma unroll
    for (int rep = 0; rep < 4; rep++) {
        int i = blockIdx.x * 256 + threadIdx.x + rep * stride;
        if (i < N4X) {
            float4 v = ((const float4*)x)[i];
            uint32_t h0, l0, h1, l1;
            split2h(v.x, v.y, h0, l0);
            split2h(v.z, v.w, h1, l1);
            ((uint32_t*)xh)[2 * i] = h0;  ((uint32_t*)xh)[2 * i + 1] = h1;
            ((uint32_t*)xl)[2 * i] = l0;  ((uint32_t*)xl)[2 * i + 1] = l1;
        } else {
            int t = i - N4X;
            int j = t >> 18;
            int w = t & (N4W - 1);
            const float* src = (j == 0) ? Wq : (j == 1) ? Wk : (j == 2) ? Wv : Wo;
            float4 v = ((const float4*)src)[w];
            __half2* dst = (__half2*)(wh + (size_t)j * WN);
            dst[2 * w] = __floats2half2_rn(v.x, v.y);
            dst[2 * w + 1] = __floats2half2_rn(v.z, v.w);
        }
    }
}

// ---------------------------------------------------------------------------
// GEMM core: 128x128 C tile, BK=64 chunks (32 chunks: hi half then lo half),
// 3-stage cp.async ring, ONE __syncthreads per chunk.
// All per-thread addresses hoisted out of the mainloop (32-bit offsets).
// ---------------------------------------------------------------------------
#define GK 1024
#define GLD 72                          // row stride in fp16 (144 B, conflict-free)
#define GTB  (128 * GLD * 2)            // 18432 B per matrix tile
#define GSTB (2 * GTB)                  // 36864 B per stage (A + B)
#define GEMM_SMEM (3 * GSTB)            // 110592 B -> 2 CTAs/SM
#define NCH 32

struct GemmCore {
    uint32_t smb;
    int lane, wr, wc;
    uint32_t dstA[4];                   // smem dst byte offsets (A; W = +GTB)
    uint32_t offA[4], offW[4];          // gmem element offsets (32-bit)
    uint32_t aRow[4], bRow[2];          // LDSM smem row byte offsets
    float acc[4][4][4];

    __device__ __forceinline__ void init(uint32_t smb_, int tid, int bm, int bn) {
        smb = smb_;
        const int wid = tid >> 5;
        lane = tid & 31;
        wr = (wid & 1) * 64; wc = (wid >> 1) * 32;
#pragma unroll
        for (int it = 0; it < 4; it++) {
            int idx = tid + it * 256;
            int r = idx >> 3, u = idx & 7;
            dstA[it] = (uint32_t)(r * GLD) * 2 + u * 16;
            offA[it] = (uint32_t)(bm + r) * GK + u * 8;
            offW[it] = (uint32_t)(bn + r) * GK + u * 8;
        }
#pragma unroll
        for (int mt = 0; mt < 4; mt++)
            aRow[mt] = (uint32_t)((wr + mt * 16 + (lane & 15)) * GLD) * 2 + (lane >> 4) * 16;
#pragma unroll
        for (int ng = 0; ng < 2; ng++)
            bRow[ng] = GTB + (uint32_t)((wc + ng * 16 + (lane & 15)) * GLD) * 2 + (lane >> 4) * 16;
#pragma unroll
        for (int mt = 0; mt < 4; mt++)
#pragma unroll
            for (int j = 0; j < 4; j++)
#pragma unroll
                for (int r = 0; r < 4; r++) acc[mt][j][r] = 0.0f;
    }
    __device__ __forceinline__ void load_chunk(
        const __half* __restrict__ Ahi, const __half* __restrict__ Alo,
        const __half* __restrict__ W, int c, int stg) {
        const __half* Ap = ((c >= 16) ? Alo : Ahi) + (c & 15) * 64;
        const __half* Wp = W + (c & 15) * 64;
        const uint32_t sa = smb + stg * GSTB;
#pragma unroll
        for (int it = 0; it < 4; it++)
            CP16(sa + dstA[it], Ap + offA[it]);
#pragma unroll
        for (int it = 0; it < 4; it++)
            CP16(sa + GTB + dstA[it], Wp + offW[it]);
    }
    __device__ __forceinline__ void compute(int stg) {
        const uint32_t sa = smb + stg * GSTB;
#pragma unroll
        for (int ks = 0; ks < 4; ks++) {
            const uint32_t colb = ks * 32;
            uint32_t a[4][4], b[2][4];
#pragma unroll
            for (int mt = 0; mt < 4; mt++)
                LDSM4(a[mt][0], a[mt][1], a[mt][2], a[mt][3], sa + aRow[mt] + colb);
#pragma unroll
            for (int ng = 0; ng < 2; ng++)
                LDSM4(b[ng][0], b[ng][1], b[ng][2], b[ng][3], sa + bRow[ng] + colb);
#pragma unroll
            for (int mt = 0; mt < 4; mt++)
#pragma unroll
                for (int j = 0; j < 4; j++)
                    MMA_F16(acc[mt][j], a[mt], b[j >> 1][j & 1], b[j >> 1][(j & 1) + 2]);
        }
    }
    __device__ __forceinline__ void run(
        const __half* __restrict__ Ahi, const __half* __restrict__ Alo,
        const __half* __restrict__ W) {
        load_chunk(Ahi, Alo, W, 0, 0); CP_COMMIT();
        load_chunk(Ahi, Alo, W, 1, 1); CP_COMMIT();
        for (int c = 0; c < NCH; c++) {
            CP_WAIT(1);
            __syncthreads();
            if (c + 2 < NCH) load_chunk(Ahi, Alo, W, c + 2, (c + 2) % 3);
            CP_COMMIT();
            compute(c % 3);
        }
    }
};

// ---------------------------------------------------------------------------
// Fused QKV GEMM: N=3072 over contiguous Wq|Wk|Wv. bn>>10 selects output:
// 0 -> Q (fp16 hi+lo), 1 -> K (hi), 2 -> V (hi).
// ---------------------------------------------------------------------------
__global__ __launch_bounds__(256, 2) void gemm_qkv(
    const __half* __restrict__ Ahi, const __half* __restrict__ Alo,
    const __half* __restrict__ W,
    const float* __restrict__ bq, const float* __restrict__ bk,
    const float* __restrict__ bv,
    __half* __restrict__ Qh, __half* __restrict__ Ql,
    __half* __restrict__ Kh, __half* __restrict__ Vh)
{
    extern __shared__ __align__(128) char smg[];
    const int bn = blockIdx.x * 128;            // 0..2944
    const int bm = blockIdx.y * 128;
    GemmCore g;
    g.init(smem_u32(smg), threadIdx.x, bm, bn);
    g.run(Ahi, Alo, W);

    const int bh = bn >> 10;                    // 0:Q 1:K 2:V
    const int cb = bn & 1023;
    const float* bias = (bh == 0) ? bq : (bh == 1) ? bk : bv;
    const int rq = g.lane >> 2;
    const int cq = (g.lane & 3) * 2;
#pragma unroll
    for (int mt = 0; mt < 4; mt++) {
#pragma unroll
        for (int j = 0; j < 4; j++) {
            const int col = cb + g.wc + j * 8 + cq;
            const float b0 = bias[col], b1 = bias[col + 1];
            const int row0 = bm + g.wr + mt * 16 + rq;
            float v0 = g.acc[mt][j][0] + b0, v1 = g.acc[mt][j][1] + b1;
            float v2 = g.acc[mt][j][2] + b0, v3 = g.acc[mt][j][3] + b1;
            if (bh == 0) {
                uint32_t h01, l01;
                split2h(v0, v1, h01, l01);
                *(uint32_t*)(Qh + (size_t)row0 * D_MODEL + col) = h01;
                *(uint32_t*)(Ql + (size_t)row0 * D_MODEL + col) = l01;
                split2h(v2, v3, h01, l01);
                *(uint32_t*)(Qh + (size_t)(row0 + 8) * D_MODEL + col) = h01;
                *(uint32_t*)(Ql + (size_t)(row0 + 8) * D_MODEL + col) = l01;
            } else {
                __half* dst = (bh == 1) ? Kh : Vh;
                *(__half2*)(dst + (size_t)row0 * D_MODEL + col) = __floats2half2_rn(v0, v1);
                *(__half2*)(dst + (size_t)(row0 + 8) * D_MODEL + col) = __floats2half2_rn(v2, v3);
            }
        }
    }
}

// ---------------------------------------------------------------------------
// Output projection GEMM: fp32 out + bias, N=1024.
// ---------------------------------------------------------------------------
__global__ __launch_bounds__(256, 2) void gemm_out(
    const __half* __restrict__ Ahi, const __half* __restrict__ Alo,
    const __half* __restrict__ W,
    const float* __restrict__ bias, float* __restrict__ C)
{
    extern __shared__ __align__(128) char smg[];
    const int bn = blockIdx.x * 128;
    const int bm = blockIdx.y * 128;
    GemmCore g;
    g.init(smem_u32(smg), threadIdx.x, bm, bn);
    g.run(Ahi, Alo, W);

    const int rq = g.lane >> 2;
    const int cq = (g.lane & 3) * 2;
#pragma unroll
    for (int mt = 0; mt < 4; mt++) {
#pragma unroll
        for (int j = 0; j < 4; j++) {
            const int col = bn + g.wc + j * 8 + cq;
            const float b0 = bias[col], b1 = bias[col + 1];
            const int row0 = bm + g.wr + mt * 16 + rq;
            *(float2*)(C + (size_t)row0 * D_MODEL + col) =
                make_float2(g.acc[mt][j][0] + b0, g.acc[mt][j][1] + b1);
            *(float2*)(C + (size_t)(row0 + 8) * D_MODEL + col) =
                make_float2(g.acc[mt][j][2] + b0, g.acc[mt][j][3] + b1);
        }
    }
}

// ---------------------------------------------------------------------------
// Flash attention, fp16 mma.sync, causal. Paired Q tiles (balanced wave).
// S = (qh+ql) K^T (2-term);  PV = P V with single-fp16 P (1 term).
// 3-stage KV ring, 2 CTAs/SM.
// ---------------------------------------------------------------------------
#define ALD 72
#define AQ_B  (128 * ALD * 2)          // 18432 B per Q matrix
#define AM_B  (64 * ALD * 2)           // 9216 B per K/V matrix
#define AST_B (2 * AM_B)               // stage: Kh,Vh = 18432 B
#define ATTN_SMEM (2 * AQ_B + 3 * AST_B)   // 92160 B -> 2 CTAs/SM

#define SCL 0.18033688f                // 0.125 * log2(e)

__global__ __launch_bounds__(256, 2) void attn_mma(
    const __half* __restrict__ Qhi, const __half* __restrict__ Qlo,
    const __half* __restrict__ Kh, const __half* __restrict__ Vh,
    __half* __restrict__ Ohi, __half* __restrict__ Olo)
{
    extern __shared__ __align__(128) char smc[];
    const uint32_t smb = smem_u32(smc);
    const int tid = threadIdx.x;
    const int wid = tid >> 5;
    const int lane = tid & 31;
    const int bx = blockIdx.x;
    const int h = blockIdx.y, b = blockIdx.z;
    const size_t rc0 = (size_t)b * SEQ * D_MODEL + h * HDIM;

    const int wr = wid * 16;
    const uint32_t lrow = lane & 15;
    const uint32_t lc16 = (lane >> 4) * 16;

    auto load_q = [&](int q0) {
#pragma unroll
        for (int it = 0; it < 8; it++) {
            int t = tid + it * 256;
            const __half* src = (t < 1024) ? Qhi : Qlo;
            uint32_t moff = (t < 1024) ? 0u : (uint32_t)AQ_B;
            int idx = t & 1023, r = idx >> 3, u = idx & 7;
            CP16(smb + moff + (uint32_t)(r * ALD + u * 8) * 2,
                 src + rc0 + (size_t)(q0 + r) * D_MODEL + u * 8);
        }
    };
    auto load_kv = [&](int kt, int stg) {
        const uint32_t sb = smb + 2 * AQ_B + stg * AST_B;
#pragma unroll
        for (int it = 0; it < 4; it++) {
            int t = tid + it * 256;
            int mtx = t >> 9;                       // 0:Kh 1:Vh
            int idx = t & 511, r = idx >> 3, u = idx & 7;
            const __half* src = (mtx == 0) ? Kh : Vh;
            CP16(sb + mtx * AM_B + (uint32_t)(r * ALD + u * 8) * 2,
                 src + rc0 + (size_t)(kt * 64 + r) * D_MODEL + u * 8);
        }
    };

    for (int half = 0; half < 2; half++) {
        const int qt = half ? (7 - bx) : (8 + bx);
        const int q0 = qt * 128;
        const int ktEnd = 2 * qt + 2;

        float o[8][4];
#pragma unroll
        for (int nt = 0; nt < 8; nt++)
#pragma unroll
            for (int c = 0; c < 4; c++) o[nt][c] = 0.0f;
        float m0 = -1e30f, m1 = -1e30f, l0 = 0.0f, l1 = 0.0f;
        uint32_t qh[4][4];

        load_q(q0);
        load_kv(0, 0);
        CP_COMMIT();
        if (1 < ktEnd) load_kv(1, 1);
        CP_COMMIT();

        for (int kt = 0; kt < ktEnd; kt++) {
            CP_WAIT(1);
            __syncthreads();
            if (kt + 2 < ktEnd) load_kv(kt + 2, (kt + 2) % 3);
            CP_COMMIT();

            if (kt == 0) {
#pragma unroll
                for (int ks = 0; ks < 4; ks++) {
                    uint32_t a1 = smb + (uint32_t)((wr + lrow) * ALD) * 2 + ks * 32 + lc16;
                    LDSM4(qh[ks][0], qh[ks][1], qh[ks][2], qh[ks][3], a1);
                }
            }

            const uint32_t sb = smb + 2 * AQ_B + (kt % 3) * AST_B;

            // ---- S = (qh+ql) K^T  (ql reloaded from smem) ----
            float s[8][4];
#pragma unroll
            for (int nt = 0; nt < 8; nt++)
#pragma unroll
                for (int c = 0; c < 4; c++) s[nt][c] = 0.0f;

#pragma unroll
            for (int ks = 0; ks < 4; ks++) {
                uint32_t kf[4][4];
#pragma unroll
                for (int ng = 0; ng < 4; ng++) {
                    uint32_t a1 = sb + (uint32_t)((ng * 16 + lrow) * ALD) * 2 + ks * 32 + lc16;
                    LDSM4(kf[ng][0], kf[ng][1], kf[ng][2], kf[ng][3], a1);
                }
                uint32_t ql[4];
                uint32_t aq = smb + AQ_B + (uint32_t)((wr + lrow) * ALD) * 2 + ks * 32 + lc16;
                LDSM4(ql[0], ql[1], ql[2], ql[3], aq);
#pragma unroll
                for (int nt = 0; nt < 8; nt++) {
                    MMA_F16(s[nt], qh[ks], kf[nt >> 1][nt & 1], kf[nt >> 1][(nt & 1) + 2]);
                    MMA_F16(s[nt], ql, kf[nt >> 1][nt & 1], kf[nt >> 1][(nt & 1) + 2]);
                }
            }

#pragma unroll
            for (int nt = 0; nt < 8; nt++)
#pragma unroll
                for (int c = 0; c < 4; c++) s[nt][c] *= SCL;   // log2-domain

            // ---- causal mask (diagonal tiles only) ----
            if (kt * 64 + 63 > q0 + wr) {
                const int r0 = q0 + wr + (lane >> 2);
#pragma unroll
                for (int nt = 0; nt < 8; nt++) {
                    const int c0 = kt * 64 + nt * 8 + 2 * (lane & 3);
                    if (c0 > r0)         s[nt][0] = -1e30f;
                    if (c0 + 1 > r0)     s[nt][1] = -1e30f;
                    if (c0 > r0 + 8)     s[nt][2] = -1e30f;
                    if (c0 + 1 > r0 + 8) s[nt][3] = -1e30f;
                }
            }

            // ---- online softmax (base-2, quad shuffles) ----
            float mx0 = -1e30f, mx1 = -1e30f;
#pragma unroll
            for (int nt = 0; nt < 8; nt++) {
                mx0 = fmaxf(mx0, fmaxf(s[nt][0], s[nt][1]));
                mx1 = fmaxf(mx1, fmaxf(s[nt][2], s[nt][3]));
            }
            mx0 = fmaxf(mx0, __shfl_xor_sync(0xffffffffu, mx0, 1));
            mx0 = fmaxf(mx0, __shfl_xor_sync(0xffffffffu, mx0, 2));
            mx1 = fmaxf(mx1, __shfl_xor_sync(0xffffffffu, mx1, 1));
            mx1 = fmaxf(mx1, __shfl_xor_sync(0xffffffffu, mx1, 2));
            const float n0 = fmaxf(m0, mx0), n1 = fmaxf(m1, mx1);
            const float cr0 = exp2f(m0 - n0), cr1 = exp2f(m1 - n1);
            m0 = n0; m1 = n1;
            float sum0 = 0.0f, sum1 = 0.0f;
#pragma unroll
            for (int nt = 0; nt < 8; nt++) {
                s[nt][0] = exp2f(s[nt][0] - n0); sum0 += s[nt][0];
                s[nt][1] = exp2f(s[nt][1] - n0); sum0 += s[nt][1];
                s[nt][2] = exp2f(s[nt][2] - n1); sum1 += s[nt][2];
                s[nt][3] = exp2f(s[nt][3] - n1); sum1 += s[nt][3];
            }
            sum0 += __shfl_xor_sync(0xffffffffu, sum0, 1);
            sum0 += __shfl_xor_sync(0xffffffffu, sum0, 2);
            sum1 += __shfl_xor_sync(0xffffffffu, sum1, 1);
            sum1 += __shfl_xor_sync(0xffffffffu, sum1, 2);
            l0 = l0 * cr0 + sum0;
            l1 = l1 * cr1 + sum1;
#pragma unroll
            for (int nt = 0; nt < 8; nt++) {
                o[nt][0] *= cr0; o[nt][1] *= cr0;
                o[nt][2] *= cr1; o[nt][3] *= cr1;
            }

            // ---- P fragments: single fp16 ----
            uint32_t ph[4][4];
#pragma unroll
            for (int ks = 0; ks < 4; ks++) {
                ph[ks][0] = pack2h(s[2 * ks][0], s[2 * ks][1]);
                ph[ks][1] = pack2h(s[2 * ks][2], s[2 * ks][3]);
                ph[ks][2] = pack2h(s[2 * ks + 1][0], s[2 * ks + 1][1]);
                ph[ks][3] = pack2h(s[2 * ks + 1][2], s[2 * ks + 1][3]);
            }

            // ---- O += P V (1 term) ----
#pragma unroll
            for (int ks = 0; ks < 4; ks++) {
                uint32_t vh[4][4];
#pragma unroll
                for (int ng = 0; ng < 4; ng++) {
                    uint32_t a1 = sb + AM_B + (uint32_t)((ks * 16 + lrow) * ALD) * 2 + ng * 32 + lc16;
                    LDSM4T(vh[ng][0], vh[ng][1], vh[ng][2], vh[ng][3], a1);
                }
#pragma unroll
                for (int nt = 0; nt < 8; nt++)
                    MMA_F16(o[nt], ph[ks], vh[nt >> 1][(nt & 1) * 2], vh[nt >> 1][(nt & 1) * 2 + 1]);
            }
        }

        // ---- epilogue: normalize, exact-split to fp16 hi/lo ----
        const float i0 = 1.0f / l0, i1 = 1.0f / l1;
        const size_t r0 = (size_t)(b * SEQ + q0 + wr + (lane >> 2));
        const int colb = h * HDIM + 2 * (lane & 3);
#pragma unroll
        for (int nt = 0; nt < 8; nt++) {
            const int col = colb + nt * 8;
            uint32_t h01, l01;
            split2h(o[nt][0] * i0, o[nt][1] * i0, h01, l01);
            *(uint32_t*)(Ohi + r0 * D_MODEL + col) = h01;
            *(uint32_t*)(Olo + r0 * D_MODEL + col) = l01;
            split2h(o[nt][2] * i1, o[nt][3] * i1, h01, l01);
            *(uint32_t*)(Ohi + (r0 + 8) * D_MODEL + col) = h01;
            *(uint32_t*)(Olo + (r0 + 8) * D_MODEL + col) = l01;
        }

        // drain before next tile reuses Q/KV smem
        CP_WAIT(0);
        __syncthreads();
    }
}

// ---------------------------------------------------------------------------
// Launch
// ---------------------------------------------------------------------------
extern "C" void kernel_launch(void* const* d_in, const int* in_sizes, int n_in,
                              void* d_out, int out_size)
{
    (void)in_sizes; (void)n_in; (void)out_size;
    const float* x  = (const float*)d_in[0];
    const float* Wq = (const float*)d_in[1];
    const float* bq = (const float*)d_in[2];
    const float* Wk = (const float*)d_in[3];
    const float* bk = (const float*)d_in[4];
    const float* Wv = (const float*)d_in[5];
    const float* bv = (const float*)d_in[6];
    const float* Wo = (const float*)d_in[7];
    const float* bo = (const float*)d_in[8];
    float* out = (float*)d_out;

    __half *xh, *xl, *wh, *qh, *ql, *kh, *vh, *oh, *ol;
    cudaGetSymbolAddress((void**)&xh, g_xh);
    cudaGetSymbolAddress((void**)&xl, g_xl);
    cudaGetSymbolAddress((void**)&wh, g_wh);
    cudaGetSymbolAddress((void**)&qh, g_qh);
    cudaGetSymbolAddress((void**)&ql, g_ql);
    cudaGetSymbolAddress((void**)&kh, g_kh);
    cudaGetSymbolAddress((void**)&vh, g_vh);
    cudaGetSymbolAddress((void**)&oh, g_oh);
    cudaGetSymbolAddress((void**)&ol, g_ol);

    cudaFuncSetAttribute(attn_mma,
                         cudaFuncAttributeMaxDynamicSharedMemorySize, ATTN_SMEM);
    cudaFuncSetAttribute(gemm_qkv,
                         cudaFuncAttributeMaxDynamicSharedMemorySize, GEMM_SMEM);
    cudaFuncSetAttribute(gemm_out,
                         cudaFuncAttributeMaxDynamicSharedMemorySize, GEMM_SMEM);

    prep_kernel<<<PREP_BLOCKS, 256>>>(x, Wq, Wk, Wv, Wo, xh, xl, wh);

    dim3 gQKV(3 * D_MODEL / 128, MTOT / 128);   // (24, 32)
    gemm_qkv<<<gQKV, 256, GEMM_SMEM>>>(xh, xl, wh, bq, bk, bv, qh, ql, kh, vh);

    dim3 gAttn(SEQ / 256, NHEAD, BATCH);        // (8, 16, 2) - paired tiles
    attn_mma<<<gAttn, 256, ATTN_SMEM>>>(qh, ql, kh, vh, oh, ol);

    dim3 gOut(D_MODEL / 128, MTOT / 128);       // (8, 32)
    gemm_out<<<gOut, 256, GEMM_SMEM>>>(oh, ol, wh + (size_t)3 * WN, bo, out);
}